// round 15
// baseline (speedup 1.0000x reference)
#include <cuda_runtime.h>
#include <stdint.h>
#include <math.h>

#define N_   2048
#define B_   2
#define C_   512
#define BN   (B_*N_)
#define EPSF 1e-8f
#define BIGF 1e9f
#define WPB  8          // warps per scan block

// ---------------- device scratch ----------------
__device__ float  g_f1n[BN*C_], g_f2n[BN*C_];
__device__ float4 g_xy1p[BN], g_xy2p[BN], g_xy11p[BN];   // (x, y, rb, 0)
__device__ int    g_nbA[BN*12], g_nbB[BN*12];
__device__ int    g_nn1i[BN*32];
__device__ float  g_nn1d[BN*32];
__device__ int    g_cand[BN*4];
__device__ float  g_Kc[BN*4];
__device__ int    g_sord[BN];
__device__ int    g_idx0R[4*BN];
__device__ int    g_idxA[BN], g_maskA[BN], g_idx1[BN], g_mask[BN];
__device__ unsigned g_bitsA[B_*(N_/32)], g_bitsM[B_*(N_/32)];
__device__ int    g_cnt[64];
__device__ float  g_flow[BN*2];    // simmerge output (pre-outlier)
__device__ float  g_flowF[BN*2];   // finish output (post-dedup/keep)
__device__ float  g_rowD[BN*2];
__device__ int    g_rowIdx[BN*2];
__device__ int    g_colArg[BN];
__device__ float  g_par[2];   // [0]=eps, [1]=power

// ---------------- init: params + counters + point prep + feature normalize --------
__global__ void k_init(const float* __restrict__ f1, const float* __restrict__ f2,
                       const float* __restrict__ gam, const float* __restrict__ eps,
                       const float* __restrict__ xy1, const float* __restrict__ xy2){
  int gt = blockIdx.x*blockDim.x + threadIdx.x;
  int gw = gt >> 5;
  int lane = threadIdx.x & 31;
  if (gt < 64) g_cnt[gt] = 0;
  if (gt == 64){
    float e = __fadd_rn(expf(eps[0]), 0.03f);
    float g = expf(gam[0]);
    g_par[0] = e;
    g_par[1] = __fdiv_rn(g, __fadd_rn(g, e));
  }
  if (gt < 2*BN){
    bool is1 = gt < BN;
    int row = is1 ? gt : gt - BN;
    const float* xy = is1 ? xy1 : xy2;
    float x = xy[row*2], y = xy[row*2+1];
    float4 v = make_float4(x, y, __fmaf_rn(y, y, __fmul_rn(x, x)), 0.f);
    if (is1) g_xy1p[row] = v; else g_xy2p[row] = v;
  }
  if (gw >= 2*BN) return;
  bool is1 = gw < BN;
  int row = is1 ? gw : gw - BN;
  const float* f = (is1 ? f1 : f2) + (size_t)row*C_;
  float*       o = (is1 ? g_f1n : g_f2n) + (size_t)row*C_;
  float v[16];
  float s = 0.f;
  #pragma unroll
  for (int t=0; t<16; t++){ v[t] = f[lane + 32*t]; s = __fmaf_rn(v[t], v[t], s); }
  #pragma unroll
  for (int off=16; off; off>>=1) s = __fadd_rn(s, __shfl_xor_sync(0xffffffffu, s, off));
  float n = __fadd_rn(sqrtf(s), EPSF);
  #pragma unroll
  for (int t=0; t<16; t++) o[lane + 32*t] = __fdiv_rn(v[t], n);
}

// ---------------- fallback: insertion-sort warp top-K (rare; bit-identical) --------
template<int K, bool MASKC, bool EYE, bool SQRT>
__device__ __noinline__ void warp_topk_ins(
    const float4* __restrict__ Q, const float4* __restrict__ R,
    const unsigned* __restrict__ mbits, int row, unsigned long long (&out)[K])
{
  const unsigned FULL = 0xffffffffu;
  int lane = threadIdx.x & 31;
  int b = row >> 11, i = row & (N_-1);
  float4 q = __ldg(&Q[row]);
  const float4* Rb = R + (size_t)b*N_;
  unsigned w0 = FULL, w1 = FULL;
  if (MASKC){
    const unsigned* mb = mbits + b*(N_/32);
    w0 = __ldg(&mb[lane]); w1 = __ldg(&mb[32+lane]);
  }
  unsigned long long best[K];
  #pragma unroll
  for (int s=0; s<K; s++) best[s] = 0x7F800000FFFFFFFFull;
  float dlast = __uint_as_float(0x7F800000u);
  float U     = __uint_as_float(0x7FC00000u);

  for (int t=0; t<64; t++){
    int j = lane + 32*t;
    float4 r = __ldg(&Rb[j]);
    float dt = __fmaf_rn(q.y, r.y, __fmul_rn(q.x, r.x));
    float d  = fmaxf(__fsub_rn(__fadd_rn(q.z, r.z), __fmul_rn(2.0f, dt)), 0.0f);
    if (MASKC){
      unsigned wv = __shfl_sync(FULL, (t<32)?w0:w1, t&31);
      if (!((wv>>lane)&1u)) d = BIGF;
    }
    if (EYE){ if (j == i) d = __fadd_rn(d, BIGF); }
    bool try_ins;
    if (SQRT){
      float d2pe = __fadd_rn(d, EPSF);
      try_ins = !(d2pe > U);
      if (try_ins) d = sqrtf(d2pe);
    } else try_ins = (d <= dlast);
    if (try_ins){
      unsigned long long key = ((unsigned long long)__float_as_uint(d) << 32) | (unsigned)j;
      if (key < best[K-1]){
        best[K-1] = key;
        #pragma unroll
        for (int s=K-1; s>0; s--){
          if (best[s] < best[s-1]){
            unsigned long long tmp = best[s-1]; best[s-1] = best[s]; best[s] = tmp;
          } else break;
        }
        unsigned hb = (unsigned)(best[K-1] >> 32);
        if (SQRT){
          float up = __uint_as_float(hb + 1);
          U = __fmul_ru(up, up);
        } else dlast = __uint_as_float(hb);
      }
    }
  }
  #pragma unroll
  for (int s=0; s<K; s++){
    unsigned long long c = best[0];
    unsigned long long m = c;
    #pragma unroll
    for (int off=16; off; off>>=1){
      unsigned long long o = __shfl_xor_sync(FULL, m, off);
      m = (o < m) ? o : m;
    }
    if (c == m){
      #pragma unroll
      for (int u=0; u<K-1; u++) best[u] = best[u+1];
      best[K-1] = 0x7F800000FFFFFFFFull;
    }
    out[s] = m;
  }
}

// ---------------- two-phase divergence-free exact warp top-K ----------------
template<int K, int CAP, bool MASKC, bool EYE, bool SQRT>
__device__ __forceinline__ void warp_topk2(
    const float4* __restrict__ Q, const float4* __restrict__ R,
    const unsigned* __restrict__ mbits, int row,
    unsigned long long* __restrict__ sbuf, unsigned long long (&out)[K])
{
  const unsigned FULL = 0xffffffffu;
  const unsigned long long INFK = 0x7F800000FFFFFFFFull;
  int lane = threadIdx.x & 31;
  int b = row >> 11, i = row & (N_-1);
  float4 q = __ldg(&Q[row]);
  const float4* Rb = R + (size_t)b*N_;
  unsigned w0 = FULL, w1 = FULL;
  if (MASKC){
    const unsigned* mb = mbits + b*(N_/32);
    w0 = __ldg(&mb[lane]); w1 = __ldg(&mb[32+lane]);
  }

  float mn = __uint_as_float(0x7F800000u);
  #pragma unroll 4
  for (int t=0; t<64; t++){
    int j = lane + 32*t;
    float4 r = __ldg(&Rb[j]);
    float dt = __fmaf_rn(q.y, r.y, __fmul_rn(q.x, r.x));
    float d  = fmaxf(__fsub_rn(__fadd_rn(q.z, r.z), __fmul_rn(2.0f, dt)), 0.0f);
    if (MASKC){
      unsigned wv = __shfl_sync(FULL, (t<32)?w0:w1, t&31);
      if (!((wv>>lane)&1u)) d = BIGF;
    }
    if (EYE){ if (j == i) d = __fadd_rn(d, BIGF); }
    mn = fminf(mn, d);
  }
  float v = mn, tau = 0.f;
  #pragma unroll
  for (int s=0; s<K; s++){
    float g = v;
    #pragma unroll
    for (int off=16; off; off>>=1) g = fminf(g, __shfl_xor_sync(FULL, g, off));
    tau = g;
    unsigned hit = __ballot_sync(FULL, v == g);
    if (lane == (__ffs(hit)-1)) v = __uint_as_float(0x7F800000u);
  }
  float ub = 0.f;
  if (SQRT){
    float S  = sqrtf(__fadd_rn(tau, EPSF));
    float su = __uint_as_float(__float_as_uint(S) + 1);
    ub = __fmul_ru(su, su);
  }

  int cnt = 0;
  #pragma unroll 4
  for (int t=0; t<64; t++){
    int j = lane + 32*t;
    float4 r = __ldg(&Rb[j]);
    float dt = __fmaf_rn(q.y, r.y, __fmul_rn(q.x, r.x));
    float d  = fmaxf(__fsub_rn(__fadd_rn(q.z, r.z), __fmul_rn(2.0f, dt)), 0.0f);
    if (MASKC){
      unsigned wv = __shfl_sync(FULL, (t<32)?w0:w1, t&31);
      if (!((wv>>lane)&1u)) d = BIGF;
    }
    if (EYE){ if (j == i) d = __fadd_rn(d, BIGF); }
    bool acc;
    if (SQRT) acc = (__fadd_rn(d, EPSF) < ub);
    else      acc = (d <= tau);
    unsigned bal = __ballot_sync(FULL, acc);
    if (acc){
      int pos = cnt + __popc(bal & ((1u<<lane)-1u));
      if (pos < CAP){
        float kd = SQRT ? sqrtf(__fadd_rn(d, EPSF)) : d;
        sbuf[pos] = ((unsigned long long)__float_as_uint(kd) << 32) | (unsigned)j;
      }
    }
    cnt += __popc(bal);
  }
  if (cnt > CAP){
    warp_topk_ins<K,MASKC,EYE,SQRT>(Q, R, mbits, row, out);
    return;
  }
  __syncwarp();
  unsigned long long mk[CAP/32];
  #pragma unroll
  for (int u=0; u<CAP/32; u++){
    int idx = lane + 32*u;
    mk[u] = (idx < cnt) ? sbuf[idx] : INFK;
  }
  #pragma unroll
  for (int s=0; s<K; s++){
    unsigned long long lm = mk[0]; int slot = 0;
    #pragma unroll
    for (int u=1; u<CAP/32; u++) if (mk[u] < lm){ lm = mk[u]; slot = u; }
    unsigned long long g = lm;
    #pragma unroll
    for (int off=16; off; off>>=1){
      unsigned long long o = __shfl_xor_sync(FULL, g, off);
      g = (o < g) ? o : g;
    }
    out[s] = g;
    if (lm == g){
      #pragma unroll
      for (int u=0; u<CAP/32; u++) if (u == slot) mk[u] = INFK;
    }
  }
}

// ---------------- scan bodies ----------------
__device__ __forceinline__ void knnpre_body(int row2, unsigned long long* sbw){
  if (row2 < BN){
    int row = row2;
    unsigned long long out[32];
    warp_topk2<32,256,false,false,false>(g_xy1p, g_xy1p, nullptr, row, sbw, out);
    if ((threadIdx.x & 31) == 0){
      #pragma unroll
      for (int s=0; s<32; s++){
        int jj = (int)(out[s] & 0xFFFFFFFFu);
        g_nn1i[row*32+s] = jj;
        g_nn1d[row*32+s] = __uint_as_float((unsigned)(out[s] >> 32));
        if (s < 12) g_nbA[row*12+s] = jj;
      }
    }
  } else {
    int row = row2 - BN;
    unsigned long long out[12];
    warp_topk2<12,128,false,false,false>(g_xy2p, g_xy2p, nullptr, row, sbw, out);
    if ((threadIdx.x & 31) == 0){
      #pragma unroll
      for (int s=0; s<12; s++) g_nbB[row*12+s] = (int)(out[s] & 0xFFFFFFFFu);
    }
  }
}

__device__ __forceinline__ void knn4kc_body(int row, int useflow, unsigned long long* sbw){
  int lane = threadIdx.x & 31;
  int b = row >> 11;
  const float4* Q = useflow ? g_xy11p : g_xy1p;
  unsigned long long out[4];
  warp_topk2<4,128,false,false,false>(Q, g_xy2p, nullptr, row, sbw, out);

  const float* f1 = g_f1n + (size_t)row*C_;
  float a[16];
  #pragma unroll
  for (int t=0; t<16; t++) a[t] = f1[lane + 32*t];
  float eps = g_par[0];
  #pragma unroll
  for (int c=0; c<4; c++){
    int j = (int)(out[c] & 0xFFFFFFFFu);
    const float* f2 = g_f2n + ((size_t)(b*N_ + j))*C_;
    float s = 0.f;
    #pragma unroll
    for (int t=0; t<16; t++) s = __fadd_rn(s, __fmul_rn(a[t], __ldg(&f2[lane + 32*t])));
    #pragma unroll
    for (int off=16; off; off>>=1) s = __fadd_rn(s, __shfl_xor_sync(0xffffffffu, s, off));
    if (lane == 0){
      g_cand[row*4+c] = j;
      g_Kc[row*4+c] = expf(__fdiv_rn(-(__fsub_rn(1.0f, s)), eps));
    }
  }
  if (lane == 0){
    int k0 = ((int)(out[0]&0xFFFFFFFFu)<<2)|0, k1 = ((int)(out[1]&0xFFFFFFFFu)<<2)|1;
    int k2 = ((int)(out[2]&0xFFFFFFFFu)<<2)|2, k3 = ((int)(out[3]&0xFFFFFFFFu)<<2)|3;
    int t;
    if (k0>k1){t=k0;k0=k1;k1=t;} if (k2>k3){t=k2;k2=k3;k3=t;}
    if (k0>k2){t=k0;k0=k2;k2=t;} if (k1>k3){t=k1;k1=k3;k3=t;}
    if (k1>k2){t=k1;k1=k2;k2=t;}
    g_sord[row] = (k0&3) | ((k1&3)<<2) | ((k2&3)<<4) | ((k3&3)<<6);
  }
}

// merged independent pre-scans: knn4kc(pass0) blocks [0,512), knnpre blocks [512,1536)
__global__ void k_pre0(){
  __shared__ unsigned long long sb[WPB*256];
  int w = threadIdx.x >> 5;
  if (blockIdx.x < BN/WPB){
    int row = blockIdx.x*WPB + w;
    knn4kc_body(row, 0, sb + w*256);
  } else {
    int row2 = (blockIdx.x - BN/WPB)*WPB + w;
    knnpre_body(row2, sb + w*256);
  }
}

__global__ void k_knn4kc1(){
  __shared__ unsigned long long sb[WPB*128];
  int w = threadIdx.x >> 5;
  int row = blockIdx.x*WPB + w;
  knn4kc_body(row, 1, sb + w*128);
}

// ---------------- all 4 sinkhorn rounds in one launch ----------
__global__ void k_sinkhorn_all(){
  extern __shared__ char sm[];
  unsigned long long* ck = (unsigned long long*)sm;
  float* su  = (float*)(sm + 16384);
  float* sv  = (float*)(sm + 24576);
  int*   tl  = (int*)(sm + 32768);
  int*   coff= (int*)(sm + 65536);
  int*   ccnt= (int*)(sm + 73728);
  int*   scnt= (int*)ck;
  int*   scur= scnt + N_;

  int b = blockIdx.x, r = blockIdx.y, dr0 = r + 1, tid = threadIdx.x;
  const int* cb = g_cand + b*N_*4;
  const float* Kb = g_Kc + b*N_*4;
  const int* sob = g_sord + b*N_;
  const float P = 1.0f/2048.0f;
  float pw = g_par[1];

  scnt[tid] = 0; scnt[tid+1024] = 0;
  __syncthreads();
  #pragma unroll
  for (int rr=0; rr<2; rr++){
    int i = tid + rr*1024;
    #pragma unroll
    for (int c=0; c<4; c++) atomicAdd(&scnt[cb[i*4+c]], 1);
  }
  __syncthreads();
  if (tid < 32){
    int lo = tid*64, tot = 0;
    for (int t=0; t<64; t++) tot += scnt[lo+t];
    int inc = tot;
    #pragma unroll
    for (int off=1; off<32; off<<=1){
      int v = __shfl_up_sync(0xffffffffu, inc, off);
      if (tid >= off) inc += v;
    }
    int run = inc - tot;
    for (int t=0; t<64; t++){
      coff[lo+t] = run;
      ccnt[lo+t] = scnt[lo+t];
      run += scnt[lo+t];
    }
  }
  __syncthreads();
  scur[tid] = coff[tid]; scur[tid+1024] = coff[tid+1024];
  __syncthreads();
  #pragma unroll
  for (int rr=0; rr<2; rr++){
    int i = tid + rr*1024;
    #pragma unroll
    for (int c=0; c<4; c++){
      int j = cb[i*4+c];
      int pos = atomicAdd(&scur[j], 1);
      tl[pos] = (i<<2) | c;
    }
  }
  __syncthreads();
  #pragma unroll
  for (int rr=0; rr<2; rr++){
    int col = tid + rr*1024;
    int off = coff[col], cnt = ccnt[col];
    int* L = tl + off;
    for (int a2=1; a2<cnt; a2++){
      int v = L[a2]; int p = a2-1;
      while (p >= 0 && L[p] > v){ L[p+1] = L[p]; p--; }
      L[p+1] = v;
    }
  }
  __syncthreads();

  sv[tid] = 1.f; sv[tid+1024] = 1.f;
  __syncthreads();
  for (int t=0; t<5; t++){
    #pragma unroll
    for (int rr=0; rr<2; rr++){
      int i = tid + rr*1024;
      int o = sob[i];
      float s = 0.f;
      #pragma unroll
      for (int p=0; p<4; p++){
        int sl = (o >> (2*p)) & 3;
        if (sl < dr0)
          s = __fmaf_rn(Kb[i*4+sl], sv[cb[i*4+sl]], s);
      }
      su[i] = powf(__fdiv_rn(P, __fadd_rn(s, EPSF)), pw);
    }
    __syncthreads();
    #pragma unroll
    for (int rr=0; rr<2; rr++){
      int j = tid + rr*1024;
      int off = coff[j], cnt = ccnt[j];
      float s = 0.f;
      for (int p=0; p<cnt; p++){
        int e = tl[off+p];
        int c = e & 3;
        if (c < dr0){
          int i = e >> 2;
          s = __fmaf_rn(Kb[i*4+c], su[i], s);
        }
      }
      sv[j] = powf(__fdiv_rn(P, __fadd_rn(s, EPSF)), pw);
    }
    __syncthreads();
  }

  ck[tid] = 0xFFFFFFFFull; ck[tid+1024] = 0xFFFFFFFFull;
  __syncthreads();
  #pragma unroll
  for (int rr=0; rr<2; rr++){
    int i = tid + rr*1024;
    float ui = su[i];
    for (int c=0; c<dr0; c++){
      int j = cb[i*4+c];
      float tv = __fmul_rn(__fmul_rn(ui, Kb[i*4+c]), sv[j]);
      unsigned long long key = ((unsigned long long)__float_as_uint(tv) << 32)
                             | (unsigned)(~(unsigned)i);
      atomicMax(&ck[j], key);
    }
  }
  __syncthreads();
  #pragma unroll
  for (int rr=0; rr<2; rr++){
    int i = tid + rr*1024;
    float ui = su[i];
    unsigned long long k0 = 0ull, k1 = 0ull;
    for (int c=0; c<dr0; c++){
      int j = cb[i*4+c];
      float tv = __fmul_rn(__fmul_rn(ui, Kb[i*4+c]), sv[j]);
      unsigned long long key = ((unsigned long long)__float_as_uint(tv) << 32)
                             | (unsigned)(~(unsigned)j);
      if (key > k0){ k1 = k0; k0 = key; }
      else if (key > k1){ k1 = key; }
    }
    float rv0 = __uint_as_float((unsigned)(k0 >> 32));
    float rv1 = __uint_as_float((unsigned)(k1 >> 32));
    int bj = (int)(~(unsigned)k0);
    int bi = (int)(~(unsigned)ck[bj]);
    bool ok = rv0 > __fmul_rn(1.2f, rv1);
    g_idx0R[r*BN + b*N_ + i] = (bi == i && ok) ? bj : -1;
  }
}

// ---------------- merge (+optional knn recon) + similarity verify + bitpack+count ---
template<int SIMK, int MODE>
__global__ void k_simmerge(const float* __restrict__ xy1, const float* __restrict__ xy2,
                           int r, int slot){
  int row = blockIdx.x*blockDim.x + threadIdx.x;
  int b = row / N_, i = row - b*N_;
  int m;
  if (MODE == 0) m = g_idx0R[r*BN + row];
  else if (MODE == 1){ int p = g_idx1[row]; m = (p == 0) ? g_idx0R[r*BN + row] : (p - 1); }
  else {
    float d0 = g_rowD[row*2], d1 = g_rowD[row*2+1];
    int bj = g_rowIdx[row*2];
    bool ok = __fmul_rn(d0, 1.2f) < d1;
    bool mut = (g_colArg[b*N_ + bj] == i);
    m = (ok && mut) ? bj : -1;
  }

  int outv = -1;
  if (m >= 0){
    const float* X1 = xy1 + (size_t)b*N_*2;
    const float* X2 = xy2 + (size_t)b*N_*2;
    float pix = X1[i*2], piy = X1[i*2+1];
    float pjx = X2[m*2], pjy = X2[m*2+1];
    float o1x[SIMK], o1y[SIMK], o2x[SIMK], o2y[SIMK];
    #pragma unroll
    for (int k=0; k<SIMK; k++){
      int a = g_nbA[row*12 + 1 + k];
      o1x[k] = __fsub_rn(X1[a*2],   pix);
      o1y[k] = __fsub_rn(X1[a*2+1], piy);
      int c = g_nbB[(b*N_+m)*12 + 1 + k];
      o2x[k] = __fsub_rn(X2[c*2],   pjx);
      o2y[k] = __fsub_rn(X2[c*2+1], pjy);
    }
    float colmin[SIMK];
    #pragma unroll
    for (int l=0; l<SIMK; l++) colmin[l] = 3.4e38f;
    float sum1 = 0.f;
    #pragma unroll
    for (int k=0; k<SIMK; k++){
      float rmn = 3.4e38f;
      #pragma unroll
      for (int l=0; l<SIMK; l++){
        float dx = __fsub_rn(o1x[k], o2x[l]);
        float dy = __fsub_rn(o1y[k], o2y[l]);
        float d = sqrtf(__fadd_rn(__fmaf_rn(dy, dy, __fmul_rn(dx, dx)), EPSF));
        rmn = fminf(rmn, d);
        colmin[l] = fminf(colmin[l], d);
      }
      sum1 = __fadd_rn(sum1, rmn);
    }
    float sum2 = 0.f;
    #pragma unroll
    for (int l=0; l<SIMK; l++) sum2 = __fadd_rn(sum2, colmin[l]);
    float Kf = (float)SIMK;
    float cham = __fmul_rn(0.5f, __fadd_rn(__fdiv_rn(sum1, Kf), __fdiv_rn(sum2, Kf)));
    if (cham <= 2.0f) outv = m;
  }
  g_idxA[row] = outv;
  int mm = (outv >= 0);
  g_maskA[row] = mm;
  int j = (outv >= 0) ? outv : 0;
  float mf = (float)mm;
  g_flow[row*2]   = __fmul_rn(__fsub_rn(xy2[(b*N_+j)*2],   xy1[row*2]),   mf);
  g_flow[row*2+1] = __fmul_rn(__fsub_rn(xy2[(b*N_+j)*2+1], xy1[row*2+1]), mf);
  unsigned bal = __ballot_sync(0xffffffffu, mm);
  if ((threadIdx.x & 31) == 0){
    g_bitsA[row >> 5] = bal;
    atomicAdd(&g_cnt[slot*B_ + b], __popc(bal));
  }
}

// ---------------- shared outlier core: masked top-8+eye filter + keep decision -----
__device__ __forceinline__ int outlier_keep(int row, int b, int i, int mi, int slot,
                                            unsigned long long* sbw){
  int lane = threadIdx.x & 31;
  int ei = g_nn1i[row*32+lane];
  float ed = g_nn1d[row*32+lane];
  bool okm = (ei != i) && (g_maskA[b*N_+ei] != 0);
  unsigned bal = __ballot_sync(0xffffffffu, okm);
  int avail = __popc(bal);
  int total = g_cnt[slot*B_ + b] - mi;
  int needed = total < 8 ? total : 8;

  unsigned long long out[8];
  if (avail >= needed){
    unsigned rem = bal;
    #pragma unroll
    for (int s=0; s<8; s++){
      if (rem){
        int l = __ffs(rem) - 1; rem &= rem - 1;
        float dd = __shfl_sync(0xffffffffu, ed, l);
        int jj = __shfl_sync(0xffffffffu, ei, l);
        out[s] = ((unsigned long long)__float_as_uint(dd) << 32) | (unsigned)jj;
      } else out[s] = 0x7F800000FFFFFFFFull;
    }
  } else {
    warp_topk2<8,128,true,true,false>(g_xy1p, g_xy1p, g_bitsA, row, sbw, out);
  }

  if (lane != 0) return 0;
  float fx = g_flow[row*2], fy = g_flow[row*2+1];
  float sx = 0.f, sy = 0.f, cnt = 0.f;
  #pragma unroll
  for (int s=0; s<8; s++){
    float d = __uint_as_float((unsigned)(out[s] >> 32));
    float vf = (d < 5e8f) ? 1.0f : 0.0f;
    int j = (d < 5e8f) ? (int)(out[s] & 0xFFFFFFFFu) : 0;
    sx = __fmaf_rn(g_flow[(b*N_+j)*2],   vf, sx);
    sy = __fmaf_rn(g_flow[(b*N_+j)*2+1], vf, sy);
    cnt = __fadd_rn(cnt, vf);
  }
  float dv = fmaxf(cnt, 1.0f);
  float mx = __fdiv_rn(sx, dv), my = __fdiv_rn(sy, dv);
  float ddx = __fsub_rn(fx, mx), ddy = __fsub_rn(fy, my);
  float dev = sqrtf(__fadd_rn(__fmaf_rn(ddy, ddy, __fmul_rn(ddx, ddx)), EPSF));
  bool keep = mi && ((cnt > 0.0f) ? (dev <= 2.0f) : true);
  return keep ? (g_idxA[row] + 1) : 0;
}

// ---------------- outlier only (sink-pass rounds) ----------
__global__ void k_outlier(int slot){
  __shared__ unsigned long long sb[WPB*128];
  int w = threadIdx.x >> 5;
  int row = blockIdx.x*WPB + w;
  if (row >= BN) return;
  int b = row >> 11, i = row & (N_-1);
  int mi = g_maskA[row];
  int v = outlier_keep(row, b, i, mi, slot, sb + w*128);
  if ((threadIdx.x & 31) == 0) g_idx1[row] = v;
}

// ---------------- outlier + finish fused (knn passes; idx1 local to row) ----------
__global__ void k_outlierF(const float* __restrict__ xy1, const float* __restrict__ xy2,
                           int slot, int slotM, float* __restrict__ outp, int withmask){
  __shared__ unsigned long long sb[WPB*128];
  int w = threadIdx.x >> 5;
  int row = blockIdx.x*WPB + w;
  if (row >= BN) return;
  int b = row >> 11, i = row & (N_-1);
  int mi = g_maskA[row];
  int v = outlier_keep(row, b, i, mi, slot, sb + w*128);
  int lane = threadIdx.x & 31;
  int mm = 0;
  if (lane == 0){
    g_idx1[row] = v;
    mm = (v != 0);
    int j = (v - 1) * mm;
    float mf = (float)mm;
    float fx = __fmul_rn(__fsub_rn(xy2[(b*N_+j)*2],   xy1[row*2]),   mf);
    float fy = __fmul_rn(__fsub_rn(xy2[(b*N_+j)*2+1], xy1[row*2+1]), mf);
    g_flowF[row*2] = fx; g_flowF[row*2+1] = fy;
    g_mask[row] = mm;
    if (outp){
      outp[row*2] = fx; outp[row*2+1] = fy;
      if (withmask) outp[2*BN + row] = mf;
    }
    atomicAdd(&g_cnt[slotM*B_ + b], mm);
  }
  if (lane == 0 && mm) atomicOr(&g_bitsM[row >> 5], 1u << (row & 31));
  if (lane == 0 && !mm) atomicAnd(&g_bitsM[row >> 5], ~(1u << (row & 31)));
}

// ---------------- dedup (+finish on final round) ----------
__global__ void k_dedup(const float* __restrict__ xy1, const float* __restrict__ xy2,
                        int dofinish, int slotM){
  __shared__ int cnt[N_+1];
  int b = blockIdx.x, tid = threadIdx.x;
  for (int s = tid; s < N_+1; s += 1024) cnt[s] = 0;
  __syncthreads();
  int v0 = g_idx1[b*N_ + tid], v1 = g_idx1[b*N_ + tid + 1024];
  atomicAdd(&cnt[v0], 1); atomicAdd(&cnt[v1], 1);
  __syncthreads();
  if (cnt[v0] > 1){ v0 = 0; g_idx1[b*N_ + tid] = 0; }
  if (cnt[v1] > 1){ v1 = 0; g_idx1[b*N_ + tid + 1024] = 0; }
  if (!dofinish) return;
  int vv[2] = {v0, v1};
  #pragma unroll
  for (int rr=0; rr<2; rr++){
    int i = tid + rr*1024, row = b*N_ + i;
    int v = vv[rr];
    int mm = (v != 0);
    int j = (v - 1) * mm;
    float mf = (float)mm;
    float fx = __fmul_rn(__fsub_rn(xy2[(b*N_+j)*2],   xy1[row*2]),   mf);
    float fy = __fmul_rn(__fsub_rn(xy2[(b*N_+j)*2+1], xy1[row*2+1]), mf);
    g_flowF[row*2] = fx; g_flowF[row*2+1] = fy;
    g_mask[row] = mm;
    unsigned bal = __ballot_sync(0xffffffffu, mm);
    if ((threadIdx.x & 31) == 0){
      g_bitsM[row >> 5] = bal;
      atomicAdd(&g_cnt[slotM*B_ + b], __popc(bal));
    }
  }
}

// ---------------- masked top-4 via list filter (+fallback) + IDW + xy11 prep -------
__global__ void k_griddata(int slot){
  __shared__ unsigned long long sb[WPB*128];
  int w = threadIdx.x >> 5;
  int lane = threadIdx.x & 31;
  int row = blockIdx.x*WPB + w;
  if (row >= BN) return;
  int b = row >> 11;

  int ei = g_nn1i[row*32+lane];
  float ed = g_nn1d[row*32+lane];
  bool okm = (g_mask[b*N_+ei] != 0);
  unsigned bal = __ballot_sync(0xffffffffu, okm);
  int avail = __popc(bal);
  int total = g_cnt[slot*B_ + b];
  int needed = total < 4 ? total : 4;

  unsigned long long out[4];
  if (avail >= needed){
    unsigned rem = bal;
    #pragma unroll
    for (int s=0; s<4; s++){
      if (rem){
        int l = __ffs(rem) - 1; rem &= rem - 1;
        float dd = __shfl_sync(0xffffffffu, ed, l);
        int jj = __shfl_sync(0xffffffffu, ei, l);
        out[s] = ((unsigned long long)__float_as_uint(dd) << 32) | (unsigned)jj;
      } else out[s] = 0x7F800000FFFFFFFFull;
    }
  } else {
    warp_topk2<4,128,true,false,false>(g_xy1p, g_xy1p, g_bitsM, row, sb + w*128, out);
  }

  if (lane == 0){
    float ws = 0.f, sx = 0.f, sy = 0.f;
    #pragma unroll
    for (int s=0; s<4; s++){
      float d = __uint_as_float((unsigned)(out[s] >> 32));
      float vf = (d < 5e8f) ? 1.0f : 0.0f;
      int j = (d < 5e8f) ? (int)(out[s] & 0xFFFFFFFFu) : 0;
      float wt = __fdiv_rn(vf, __fadd_rn(d, 1e-6f));
      sx = __fmaf_rn(wt, g_flowF[(b*N_+j)*2],   sx);
      sy = __fmaf_rn(wt, g_flowF[(b*N_+j)*2+1], sy);
      ws = __fadd_rn(ws, wt);
    }
    float ix = __fdiv_rn(sx, __fadd_rn(ws, EPSF));
    float iy = __fdiv_rn(sy, __fadd_rn(ws, EPSF));
    int m = g_mask[row];
    float gx = m ? g_flowF[row*2]   : ix;
    float gy = m ? g_flowF[row*2+1] : iy;
    float4 p = g_xy1p[row];
    float nx = __fadd_rn(p.x, gx);
    float ny = __fadd_rn(p.y, gy);
    g_xy11p[row] = make_float4(nx, ny, __fmaf_rn(ny, ny, __fmul_rn(nx, nx)), 0.f);
  }
}

// ---------------- dual knn_match scans: row top-2 and col top-1 (D space) ----------
__global__ void k_knn21(){
  __shared__ unsigned long long sb[WPB*128];
  int w = threadIdx.x >> 5;
  int row2 = blockIdx.x*WPB + w;
  if (row2 >= 2*BN) return;
  bool first = row2 < BN;
  int row = first ? row2 : row2 - BN;
  const float4* Q = first ? g_xy11p : g_xy2p;
  const float4* R = first ? g_xy2p  : g_xy11p;
  unsigned long long out[2];
  warp_topk2<2,128,false,false,true>(Q, R, nullptr, row, sb + w*128, out);
  if ((threadIdx.x & 31) == 0){
    if (first){
      g_rowIdx[row*2]   = (int)(out[0] & 0xFFFFFFFFu);
      g_rowIdx[row*2+1] = (int)(out[1] & 0xFFFFFFFFu);
      g_rowD[row*2]   = __uint_as_float((unsigned)(out[0] >> 32));
      g_rowD[row*2+1] = __uint_as_float((unsigned)(out[1] >> 32));
    } else {
      g_colArg[row] = (int)(out[0] & 0xFFFFFFFFu);
    }
  }
}

// ---------------- host orchestration ----------------
extern "C" void kernel_launch(void* const* d_in, const int* in_sizes, int n_in,
                              void* d_out, int out_size){
  const float* xy1 = (const float*)d_in[0];
  const float* xy2 = (const float*)d_in[1];
  const float* f1  = (const float*)d_in[2];
  const float* f2  = (const float*)d_in[3];
  const float* gam = (const float*)d_in[4];
  const float* eps = (const float*)d_in[5];
  float* outp = (float*)d_out;
  int withmask = (out_size >= BN*3) ? 1 : 0;

  static bool attr_done = false;
  if (!attr_done){
    cudaFuncSetAttribute(k_sinkhorn_all, cudaFuncAttributeMaxDynamicSharedMemorySize, 81920);
    attr_done = true;
  }

  const int WB = WPB*32;            // 256 threads
  const int GW = BN/WPB;            // 512 blocks
  const int GW2 = 2*BN/WPB;         // 1024 blocks
  const int TB = 256, GT = BN/TB;

  int slotA = 0;    // counts of maskA (outlier consumers)
  int slotM = 10;   // counts of mask (griddata consumers)

  k_init<<<(2*BN*32)/256, 256>>>(f1, f2, gam, eps, xy1, xy2);
  k_pre0<<<GW + GW2, WB>>>();       // knn4kc(pass0) + knnpre, independent, one launch

  // ---- two sinkhorn matching passes ----
  for (int pass = 0; pass < 2; pass++){
    if (pass) k_knn4kc1<<<GW, WB>>>();
    k_sinkhorn_all<<<dim3(B_,4), 1024, 81920>>>();
    for (int r = 0; r < 4; r++){
      if (r == 0) k_simmerge<8,0><<<GT, TB>>>(xy1, xy2, r, slotA);
      else        k_simmerge<8,1><<<GT, TB>>>(xy1, xy2, r, slotA);
      k_outlier<<<GW, WB>>>(slotA);
      slotA++;
      if (r > 0) k_dedup<<<2, 1024>>>(xy1, xy2, r == 3, slotM);
    }
    k_griddata<<<GW, WB>>>(slotM);
    slotM++;
  }

  // ---- two KNN matching passes ----
  for (int pass = 0; pass < 2; pass++){
    int final = (pass == 1);
    k_knn21<<<GW2, WB>>>();
    k_simmerge<11,2><<<GT, TB>>>(xy1, xy2, 0, slotA);
    k_outlierF<<<GW, WB>>>(xy1, xy2, slotA, slotM,
                           final ? outp : nullptr, withmask);
    slotA++;
    if (!final){
      k_griddata<<<GW, WB>>>(slotM);
      slotM++;
    }
  }
}

// round 16
// speedup vs baseline: 1.0200x; 1.0200x over previous
#include <cuda_runtime.h>
#include <stdint.h>
#include <math.h>

#define N_   2048
#define B_   2
#define C_   512
#define BN   (B_*N_)
#define EPSF 1e-8f
#define BIGF 1e9f
#define WPB  8          // warps per scan block

// ---------------- device scratch ----------------
__device__ float  g_f1n[BN*C_], g_f2n[BN*C_];
__device__ float4 g_xy1p[BN], g_xy2p[BN], g_xy11p[BN];   // (x, y, rb, 0)
__device__ int    g_nbA[BN*12], g_nbB[BN*12];
__device__ int    g_nn1i[BN*32];
__device__ float  g_nn1d[BN*32];
__device__ int    g_cand[BN*4];
__device__ float  g_Kc[BN*4];
__device__ int    g_sord[BN];
__device__ int    g_idx0R[4*BN];
__device__ int    g_idxA[BN], g_maskA[BN], g_idx1[BN], g_mask[BN];
__device__ unsigned g_bitsA[B_*(N_/32)], g_bitsM[B_*(N_/32)];
__device__ int    g_cnt[64];
__device__ float  g_flow[BN*2];    // simmerge output (pre-outlier)
__device__ float  g_flowF[BN*2];   // finish output (post-dedup/keep)
__device__ float  g_rowD[BN*2];
__device__ int    g_rowIdx[BN*2];
__device__ int    g_colArg[BN];
__device__ float  g_par[2];   // [0]=eps, [1]=power

// ---------------- init: params + counters + point prep + feature normalize --------
__global__ void k_init(const float* __restrict__ f1, const float* __restrict__ f2,
                       const float* __restrict__ gam, const float* __restrict__ eps,
                       const float* __restrict__ xy1, const float* __restrict__ xy2){
  int gt = blockIdx.x*blockDim.x + threadIdx.x;
  int gw = gt >> 5;
  int lane = threadIdx.x & 31;
  if (gt < 64) g_cnt[gt] = 0;
  if (gt == 64){
    float e = __fadd_rn(expf(eps[0]), 0.03f);
    float g = expf(gam[0]);
    g_par[0] = e;
    g_par[1] = __fdiv_rn(g, __fadd_rn(g, e));
  }
  if (gt < 2*BN){
    bool is1 = gt < BN;
    int row = is1 ? gt : gt - BN;
    const float* xy = is1 ? xy1 : xy2;
    float x = xy[row*2], y = xy[row*2+1];
    float4 v = make_float4(x, y, __fmaf_rn(y, y, __fmul_rn(x, x)), 0.f);
    if (is1) g_xy1p[row] = v; else g_xy2p[row] = v;
  }
  if (gw >= 2*BN) return;
  bool is1 = gw < BN;
  int row = is1 ? gw : gw - BN;
  const float* f = (is1 ? f1 : f2) + (size_t)row*C_;
  float*       o = (is1 ? g_f1n : g_f2n) + (size_t)row*C_;
  float v[16];
  float s = 0.f;
  #pragma unroll
  for (int t=0; t<16; t++){ v[t] = f[lane + 32*t]; s = __fmaf_rn(v[t], v[t], s); }
  #pragma unroll
  for (int off=16; off; off>>=1) s = __fadd_rn(s, __shfl_xor_sync(0xffffffffu, s, off));
  float n = __fadd_rn(sqrtf(s), EPSF);
  #pragma unroll
  for (int t=0; t<16; t++) o[lane + 32*t] = __fdiv_rn(v[t], n);
}

// ---------------- fallback: insertion-sort warp top-K (rare; bit-identical) --------
template<int K, bool MASKC, bool EYE, bool SQRT>
__device__ __noinline__ void warp_topk_ins(
    const float4* __restrict__ Q, const float4* __restrict__ R,
    const unsigned* __restrict__ mbits, int row, unsigned long long (&out)[K])
{
  const unsigned FULL = 0xffffffffu;
  int lane = threadIdx.x & 31;
  int b = row >> 11, i = row & (N_-1);
  float4 q = __ldg(&Q[row]);
  const float4* Rb = R + (size_t)b*N_;
  unsigned w0 = FULL, w1 = FULL;
  if (MASKC){
    const unsigned* mb = mbits + b*(N_/32);
    w0 = __ldg(&mb[lane]); w1 = __ldg(&mb[32+lane]);
  }
  unsigned long long best[K];
  #pragma unroll
  for (int s=0; s<K; s++) best[s] = 0x7F800000FFFFFFFFull;
  float dlast = __uint_as_float(0x7F800000u);
  float U     = __uint_as_float(0x7FC00000u);

  for (int t=0; t<64; t++){
    int j = lane + 32*t;
    float4 r = __ldg(&Rb[j]);
    float dt = __fmaf_rn(q.y, r.y, __fmul_rn(q.x, r.x));
    float d  = fmaxf(__fsub_rn(__fadd_rn(q.z, r.z), __fmul_rn(2.0f, dt)), 0.0f);
    if (MASKC){
      unsigned wv = __shfl_sync(FULL, (t<32)?w0:w1, t&31);
      if (!((wv>>lane)&1u)) d = BIGF;
    }
    if (EYE){ if (j == i) d = __fadd_rn(d, BIGF); }
    bool try_ins;
    if (SQRT){
      float d2pe = __fadd_rn(d, EPSF);
      try_ins = !(d2pe > U);
      if (try_ins) d = sqrtf(d2pe);
    } else try_ins = (d <= dlast);
    if (try_ins){
      unsigned long long key = ((unsigned long long)__float_as_uint(d) << 32) | (unsigned)j;
      if (key < best[K-1]){
        best[K-1] = key;
        #pragma unroll
        for (int s=K-1; s>0; s--){
          if (best[s] < best[s-1]){
            unsigned long long tmp = best[s-1]; best[s-1] = best[s]; best[s] = tmp;
          } else break;
        }
        unsigned hb = (unsigned)(best[K-1] >> 32);
        if (SQRT){
          float up = __uint_as_float(hb + 1);
          U = __fmul_ru(up, up);
        } else dlast = __uint_as_float(hb);
      }
    }
  }
  #pragma unroll
  for (int s=0; s<K; s++){
    unsigned long long c = best[0];
    unsigned long long m = c;
    #pragma unroll
    for (int off=16; off; off>>=1){
      unsigned long long o = __shfl_xor_sync(FULL, m, off);
      m = (o < m) ? o : m;
    }
    if (c == m){
      #pragma unroll
      for (int u=0; u<K-1; u++) best[u] = best[u+1];
      best[K-1] = 0x7F800000FFFFFFFFull;
    }
    out[s] = m;
  }
}

// ---------------- two-phase divergence-free exact warp top-K ----------------
template<int K, int CAP, bool MASKC, bool EYE, bool SQRT>
__device__ __forceinline__ void warp_topk2(
    const float4* __restrict__ Q, const float4* __restrict__ R,
    const unsigned* __restrict__ mbits, int row,
    unsigned long long* __restrict__ sbuf, unsigned long long (&out)[K])
{
  const unsigned FULL = 0xffffffffu;
  const unsigned long long INFK = 0x7F800000FFFFFFFFull;
  int lane = threadIdx.x & 31;
  int b = row >> 11, i = row & (N_-1);
  float4 q = __ldg(&Q[row]);
  const float4* Rb = R + (size_t)b*N_;
  unsigned w0 = FULL, w1 = FULL;
  if (MASKC){
    const unsigned* mb = mbits + b*(N_/32);
    w0 = __ldg(&mb[lane]); w1 = __ldg(&mb[32+lane]);
  }

  float mn = __uint_as_float(0x7F800000u);
  #pragma unroll 4
  for (int t=0; t<64; t++){
    int j = lane + 32*t;
    float4 r = __ldg(&Rb[j]);
    float dt = __fmaf_rn(q.y, r.y, __fmul_rn(q.x, r.x));
    float d  = fmaxf(__fsub_rn(__fadd_rn(q.z, r.z), __fmul_rn(2.0f, dt)), 0.0f);
    if (MASKC){
      unsigned wv = __shfl_sync(FULL, (t<32)?w0:w1, t&31);
      if (!((wv>>lane)&1u)) d = BIGF;
    }
    if (EYE){ if (j == i) d = __fadd_rn(d, BIGF); }
    mn = fminf(mn, d);
  }
  float v = mn, tau = 0.f;
  #pragma unroll
  for (int s=0; s<K; s++){
    float g = v;
    #pragma unroll
    for (int off=16; off; off>>=1) g = fminf(g, __shfl_xor_sync(FULL, g, off));
    tau = g;
    unsigned hit = __ballot_sync(FULL, v == g);
    if (lane == (__ffs(hit)-1)) v = __uint_as_float(0x7F800000u);
  }
  float ub = 0.f;
  if (SQRT){
    float S  = sqrtf(__fadd_rn(tau, EPSF));
    float su = __uint_as_float(__float_as_uint(S) + 1);
    ub = __fmul_ru(su, su);
  }

  int cnt = 0;
  #pragma unroll 4
  for (int t=0; t<64; t++){
    int j = lane + 32*t;
    float4 r = __ldg(&Rb[j]);
    float dt = __fmaf_rn(q.y, r.y, __fmul_rn(q.x, r.x));
    float d  = fmaxf(__fsub_rn(__fadd_rn(q.z, r.z), __fmul_rn(2.0f, dt)), 0.0f);
    if (MASKC){
      unsigned wv = __shfl_sync(FULL, (t<32)?w0:w1, t&31);
      if (!((wv>>lane)&1u)) d = BIGF;
    }
    if (EYE){ if (j == i) d = __fadd_rn(d, BIGF); }
    bool acc;
    if (SQRT) acc = (__fadd_rn(d, EPSF) < ub);
    else      acc = (d <= tau);
    unsigned bal = __ballot_sync(FULL, acc);
    if (acc){
      int pos = cnt + __popc(bal & ((1u<<lane)-1u));
      if (pos < CAP){
        float kd = SQRT ? sqrtf(__fadd_rn(d, EPSF)) : d;
        sbuf[pos] = ((unsigned long long)__float_as_uint(kd) << 32) | (unsigned)j;
      }
    }
    cnt += __popc(bal);
  }
  if (cnt > CAP){
    warp_topk_ins<K,MASKC,EYE,SQRT>(Q, R, mbits, row, out);
    return;
  }
  __syncwarp();
  unsigned long long mk[CAP/32];
  #pragma unroll
  for (int u=0; u<CAP/32; u++){
    int idx = lane + 32*u;
    mk[u] = (idx < cnt) ? sbuf[idx] : INFK;
  }
  #pragma unroll
  for (int s=0; s<K; s++){
    unsigned long long lm = mk[0]; int slot = 0;
    #pragma unroll
    for (int u=1; u<CAP/32; u++) if (mk[u] < lm){ lm = mk[u]; slot = u; }
    unsigned long long g = lm;
    #pragma unroll
    for (int off=16; off; off>>=1){
      unsigned long long o = __shfl_xor_sync(FULL, g, off);
      g = (o < g) ? o : g;
    }
    out[s] = g;
    if (lm == g){
      #pragma unroll
      for (int u=0; u<CAP/32; u++) if (u == slot) mk[u] = INFK;
    }
  }
}

// ---------------- precompute: top-32 self list on xy1 (+nbA), top-12 on xy2 --------
__global__ void k_knnpre(){
  __shared__ unsigned long long sb[WPB*256];
  int w = threadIdx.x >> 5;
  int row2 = blockIdx.x*WPB + w;
  if (row2 >= 2*BN) return;
  if (row2 < BN){
    int row = row2;
    unsigned long long out[32];
    warp_topk2<32,256,false,false,false>(g_xy1p, g_xy1p, nullptr, row, sb + w*256, out);
    if ((threadIdx.x & 31) == 0){
      #pragma unroll
      for (int s=0; s<32; s++){
        int jj = (int)(out[s] & 0xFFFFFFFFu);
        g_nn1i[row*32+s] = jj;
        g_nn1d[row*32+s] = __uint_as_float((unsigned)(out[s] >> 32));
        if (s < 12) g_nbA[row*12+s] = jj;
      }
    }
  } else {
    int row = row2 - BN;
    unsigned long long out[12];
    warp_topk2<12,128,false,false,false>(g_xy2p, g_xy2p, nullptr, row, sb + w*256, out);
    if ((threadIdx.x & 31) == 0){
      #pragma unroll
      for (int s=0; s<12; s++) g_nbB[row*12+s] = (int)(out[s] & 0xFFFFFFFFu);
    }
  }
}

// ---------------- knn4 candidates + feature K entries + slot order (fused) --------
__global__ void k_knn4kc(int useflow){
  __shared__ unsigned long long sb[WPB*128];
  int w = threadIdx.x >> 5;
  int lane = threadIdx.x & 31;
  int row = blockIdx.x*WPB + w;
  if (row >= BN) return;
  int b = row >> 11;
  const float4* Q = useflow ? g_xy11p : g_xy1p;
  unsigned long long out[4];
  warp_topk2<4,128,false,false,false>(Q, g_xy2p, nullptr, row, sb + w*128, out);

  const float* f1 = g_f1n + (size_t)row*C_;
  float a[16];
  #pragma unroll
  for (int t=0; t<16; t++) a[t] = f1[lane + 32*t];
  float eps = g_par[0];
  #pragma unroll
  for (int c=0; c<4; c++){
    int j = (int)(out[c] & 0xFFFFFFFFu);
    const float* f2 = g_f2n + ((size_t)(b*N_ + j))*C_;
    float s = 0.f;
    #pragma unroll
    for (int t=0; t<16; t++) s = __fadd_rn(s, __fmul_rn(a[t], __ldg(&f2[lane + 32*t])));
    #pragma unroll
    for (int off=16; off; off>>=1) s = __fadd_rn(s, __shfl_xor_sync(0xffffffffu, s, off));
    if (lane == 0){
      g_cand[row*4+c] = j;
      g_Kc[row*4+c] = expf(__fdiv_rn(-(__fsub_rn(1.0f, s)), eps));
    }
  }
  if (lane == 0){
    int k0 = ((int)(out[0]&0xFFFFFFFFu)<<2)|0, k1 = ((int)(out[1]&0xFFFFFFFFu)<<2)|1;
    int k2 = ((int)(out[2]&0xFFFFFFFFu)<<2)|2, k3 = ((int)(out[3]&0xFFFFFFFFu)<<2)|3;
    int t;
    if (k0>k1){t=k0;k0=k1;k1=t;} if (k2>k3){t=k2;k2=k3;k3=t;}
    if (k0>k2){t=k0;k0=k2;k2=t;} if (k1>k3){t=k1;k1=k3;k3=t;}
    if (k1>k2){t=k1;k1=k2;k2=t;}
    g_sord[row] = (k0&3) | ((k1&3)<<2) | ((k2&3)<<4) | ((k3&3)<<6);
  }
}

// ---------------- all 4 sinkhorn rounds in one launch ----------
__global__ void k_sinkhorn_all(){
  extern __shared__ char sm[];
  unsigned long long* ck = (unsigned long long*)sm;
  float* su  = (float*)(sm + 16384);
  float* sv  = (float*)(sm + 24576);
  int*   tl  = (int*)(sm + 32768);
  int*   coff= (int*)(sm + 65536);
  int*   ccnt= (int*)(sm + 73728);
  int*   scnt= (int*)ck;
  int*   scur= scnt + N_;

  int b = blockIdx.x, r = blockIdx.y, dr0 = r + 1, tid = threadIdx.x;
  const int* cb = g_cand + b*N_*4;
  const float* Kb = g_Kc + b*N_*4;
  const int* sob = g_sord + b*N_;
  const float P = 1.0f/2048.0f;
  float pw = g_par[1];

  scnt[tid] = 0; scnt[tid+1024] = 0;
  __syncthreads();
  #pragma unroll
  for (int rr=0; rr<2; rr++){
    int i = tid + rr*1024;
    #pragma unroll
    for (int c=0; c<4; c++) atomicAdd(&scnt[cb[i*4+c]], 1);
  }
  __syncthreads();
  if (tid < 32){
    int lo = tid*64, tot = 0;
    for (int t=0; t<64; t++) tot += scnt[lo+t];
    int inc = tot;
    #pragma unroll
    for (int off=1; off<32; off<<=1){
      int v = __shfl_up_sync(0xffffffffu, inc, off);
      if (tid >= off) inc += v;
    }
    int run = inc - tot;
    for (int t=0; t<64; t++){
      coff[lo+t] = run;
      ccnt[lo+t] = scnt[lo+t];
      run += scnt[lo+t];
    }
  }
  __syncthreads();
  scur[tid] = coff[tid]; scur[tid+1024] = coff[tid+1024];
  __syncthreads();
  #pragma unroll
  for (int rr=0; rr<2; rr++){
    int i = tid + rr*1024;
    #pragma unroll
    for (int c=0; c<4; c++){
      int j = cb[i*4+c];
      int pos = atomicAdd(&scur[j], 1);
      tl[pos] = (i<<2) | c;
    }
  }
  __syncthreads();
  #pragma unroll
  for (int rr=0; rr<2; rr++){
    int col = tid + rr*1024;
    int off = coff[col], cnt = ccnt[col];
    int* L = tl + off;
    for (int a2=1; a2<cnt; a2++){
      int v = L[a2]; int p = a2-1;
      while (p >= 0 && L[p] > v){ L[p+1] = L[p]; p--; }
      L[p+1] = v;
    }
  }
  __syncthreads();

  sv[tid] = 1.f; sv[tid+1024] = 1.f;
  __syncthreads();
  for (int t=0; t<5; t++){
    #pragma unroll
    for (int rr=0; rr<2; rr++){
      int i = tid + rr*1024;
      int o = sob[i];
      float s = 0.f;
      #pragma unroll
      for (int p=0; p<4; p++){
        int sl = (o >> (2*p)) & 3;
        if (sl < dr0)
          s = __fmaf_rn(Kb[i*4+sl], sv[cb[i*4+sl]], s);
      }
      su[i] = powf(__fdiv_rn(P, __fadd_rn(s, EPSF)), pw);
    }
    __syncthreads();
    #pragma unroll
    for (int rr=0; rr<2; rr++){
      int j = tid + rr*1024;
      int off = coff[j], cnt = ccnt[j];
      float s = 0.f;
      for (int p=0; p<cnt; p++){
        int e = tl[off+p];
        int c = e & 3;
        if (c < dr0){
          int i = e >> 2;
          s = __fmaf_rn(Kb[i*4+c], su[i], s);
        }
      }
      sv[j] = powf(__fdiv_rn(P, __fadd_rn(s, EPSF)), pw);
    }
    __syncthreads();
  }

  ck[tid] = 0xFFFFFFFFull; ck[tid+1024] = 0xFFFFFFFFull;
  __syncthreads();
  #pragma unroll
  for (int rr=0; rr<2; rr++){
    int i = tid + rr*1024;
    float ui = su[i];
    for (int c=0; c<dr0; c++){
      int j = cb[i*4+c];
      float tv = __fmul_rn(__fmul_rn(ui, Kb[i*4+c]), sv[j]);
      unsigned long long key = ((unsigned long long)__float_as_uint(tv) << 32)
                             | (unsigned)(~(unsigned)i);
      atomicMax(&ck[j], key);
    }
  }
  __syncthreads();
  #pragma unroll
  for (int rr=0; rr<2; rr++){
    int i = tid + rr*1024;
    float ui = su[i];
    unsigned long long k0 = 0ull, k1 = 0ull;
    for (int c=0; c<dr0; c++){
      int j = cb[i*4+c];
      float tv = __fmul_rn(__fmul_rn(ui, Kb[i*4+c]), sv[j]);
      unsigned long long key = ((unsigned long long)__float_as_uint(tv) << 32)
                             | (unsigned)(~(unsigned)j);
      if (key > k0){ k1 = k0; k0 = key; }
      else if (key > k1){ k1 = key; }
    }
    float rv0 = __uint_as_float((unsigned)(k0 >> 32));
    float rv1 = __uint_as_float((unsigned)(k1 >> 32));
    int bj = (int)(~(unsigned)k0);
    int bi = (int)(~(unsigned)ck[bj]);
    bool ok = rv0 > __fmul_rn(1.2f, rv1);
    g_idx0R[r*BN + b*N_ + i] = (bi == i && ok) ? bj : -1;
  }
}

// ---------------- merge (+optional knn recon) + similarity verify + bitpack+count ---
template<int SIMK, int MODE>
__global__ void k_simmerge(const float* __restrict__ xy1, const float* __restrict__ xy2,
                           int r, int slot){
  int row = blockIdx.x*blockDim.x + threadIdx.x;
  int b = row / N_, i = row - b*N_;
  int m;
  if (MODE == 0) m = g_idx0R[r*BN + row];
  else if (MODE == 1){ int p = g_idx1[row]; m = (p == 0) ? g_idx0R[r*BN + row] : (p - 1); }
  else {
    float d0 = g_rowD[row*2], d1 = g_rowD[row*2+1];
    int bj = g_rowIdx[row*2];
    bool ok = __fmul_rn(d0, 1.2f) < d1;
    bool mut = (g_colArg[b*N_ + bj] == i);
    m = (ok && mut) ? bj : -1;
  }

  int outv = -1;
  if (m >= 0){
    const float* X1 = xy1 + (size_t)b*N_*2;
    const float* X2 = xy2 + (size_t)b*N_*2;
    float pix = X1[i*2], piy = X1[i*2+1];
    float pjx = X2[m*2], pjy = X2[m*2+1];
    float o1x[SIMK], o1y[SIMK], o2x[SIMK], o2y[SIMK];
    #pragma unroll
    for (int k=0; k<SIMK; k++){
      int a = g_nbA[row*12 + 1 + k];
      o1x[k] = __fsub_rn(X1[a*2],   pix);
      o1y[k] = __fsub_rn(X1[a*2+1], piy);
      int c = g_nbB[(b*N_+m)*12 + 1 + k];
      o2x[k] = __fsub_rn(X2[c*2],   pjx);
      o2y[k] = __fsub_rn(X2[c*2+1], pjy);
    }
    float colmin[SIMK];
    #pragma unroll
    for (int l=0; l<SIMK; l++) colmin[l] = 3.4e38f;
    float sum1 = 0.f;
    #pragma unroll
    for (int k=0; k<SIMK; k++){
      float rmn = 3.4e38f;
      #pragma unroll
      for (int l=0; l<SIMK; l++){
        float dx = __fsub_rn(o1x[k], o2x[l]);
        float dy = __fsub_rn(o1y[k], o2y[l]);
        float d = sqrtf(__fadd_rn(__fmaf_rn(dy, dy, __fmul_rn(dx, dx)), EPSF));
        rmn = fminf(rmn, d);
        colmin[l] = fminf(colmin[l], d);
      }
      sum1 = __fadd_rn(sum1, rmn);
    }
    float sum2 = 0.f;
    #pragma unroll
    for (int l=0; l<SIMK; l++) sum2 = __fadd_rn(sum2, colmin[l]);
    float Kf = (float)SIMK;
    float cham = __fmul_rn(0.5f, __fadd_rn(__fdiv_rn(sum1, Kf), __fdiv_rn(sum2, Kf)));
    if (cham <= 2.0f) outv = m;
  }
  g_idxA[row] = outv;
  int mm = (outv >= 0);
  g_maskA[row] = mm;
  int j = (outv >= 0) ? outv : 0;
  float mf = (float)mm;
  g_flow[row*2]   = __fmul_rn(__fsub_rn(xy2[(b*N_+j)*2],   xy1[row*2]),   mf);
  g_flow[row*2+1] = __fmul_rn(__fsub_rn(xy2[(b*N_+j)*2+1], xy1[row*2+1]), mf);
  unsigned bal = __ballot_sync(0xffffffffu, mm);
  if ((threadIdx.x & 31) == 0){
    g_bitsA[row >> 5] = bal;
    atomicAdd(&g_cnt[slot*B_ + b], __popc(bal));
  }
}

// ---------------- shared outlier core: masked top-8+eye filter + keep decision -----
__device__ __forceinline__ int outlier_keep(int row, int b, int i, int mi, int slot,
                                            unsigned long long* sbw){
  int lane = threadIdx.x & 31;
  int ei = g_nn1i[row*32+lane];
  float ed = g_nn1d[row*32+lane];
  bool okm = (ei != i) && (g_maskA[b*N_+ei] != 0);
  unsigned bal = __ballot_sync(0xffffffffu, okm);
  int avail = __popc(bal);
  int total = g_cnt[slot*B_ + b] - mi;
  int needed = total < 8 ? total : 8;

  unsigned long long out[8];
  if (avail >= needed){
    unsigned rem = bal;
    #pragma unroll
    for (int s=0; s<8; s++){
      if (rem){
        int l = __ffs(rem) - 1; rem &= rem - 1;
        float dd = __shfl_sync(0xffffffffu, ed, l);
        int jj = __shfl_sync(0xffffffffu, ei, l);
        out[s] = ((unsigned long long)__float_as_uint(dd) << 32) | (unsigned)jj;
      } else out[s] = 0x7F800000FFFFFFFFull;
    }
  } else {
    warp_topk2<8,128,true,true,false>(g_xy1p, g_xy1p, g_bitsA, row, sbw, out);
  }

  if (lane != 0) return 0;
  float fx = g_flow[row*2], fy = g_flow[row*2+1];
  float sx = 0.f, sy = 0.f, cnt = 0.f;
  #pragma unroll
  for (int s=0; s<8; s++){
    float d = __uint_as_float((unsigned)(out[s] >> 32));
    float vf = (d < 5e8f) ? 1.0f : 0.0f;
    int j = (d < 5e8f) ? (int)(out[s] & 0xFFFFFFFFu) : 0;
    sx = __fmaf_rn(g_flow[(b*N_+j)*2],   vf, sx);
    sy = __fmaf_rn(g_flow[(b*N_+j)*2+1], vf, sy);
    cnt = __fadd_rn(cnt, vf);
  }
  float dv = fmaxf(cnt, 1.0f);
  float mx = __fdiv_rn(sx, dv), my = __fdiv_rn(sy, dv);
  float ddx = __fsub_rn(fx, mx), ddy = __fsub_rn(fy, my);
  float dev = sqrtf(__fadd_rn(__fmaf_rn(ddy, ddy, __fmul_rn(ddx, ddx)), EPSF));
  bool keep = mi && ((cnt > 0.0f) ? (dev <= 2.0f) : true);
  return keep ? (g_idxA[row] + 1) : 0;
}

// ---------------- outlier only (sink-pass rounds) ----------
__global__ void k_outlier(int slot){
  __shared__ unsigned long long sb[WPB*128];
  int w = threadIdx.x >> 5;
  int row = blockIdx.x*WPB + w;
  if (row >= BN) return;
  int b = row >> 11, i = row & (N_-1);
  int mi = g_maskA[row];
  int v = outlier_keep(row, b, i, mi, slot, sb + w*128);
  if ((threadIdx.x & 31) == 0) g_idx1[row] = v;
}

// ---------------- outlier + finish fused (knn passes; idx1 local to row) ----------
__global__ void k_outlierF(const float* __restrict__ xy1, const float* __restrict__ xy2,
                           int slot, int slotM, float* __restrict__ outp, int withmask){
  __shared__ unsigned long long sb[WPB*128];
  int w = threadIdx.x >> 5;
  int row = blockIdx.x*WPB + w;
  if (row >= BN) return;
  int b = row >> 11, i = row & (N_-1);
  int mi = g_maskA[row];
  int v = outlier_keep(row, b, i, mi, slot, sb + w*128);
  int lane = threadIdx.x & 31;
  int mm = 0;
  if (lane == 0){
    g_idx1[row] = v;
    mm = (v != 0);
    int j = (v - 1) * mm;
    float mf = (float)mm;
    float fx = __fmul_rn(__fsub_rn(xy2[(b*N_+j)*2],   xy1[row*2]),   mf);
    float fy = __fmul_rn(__fsub_rn(xy2[(b*N_+j)*2+1], xy1[row*2+1]), mf);
    g_flowF[row*2] = fx; g_flowF[row*2+1] = fy;
    g_mask[row] = mm;
    if (outp){
      outp[row*2] = fx; outp[row*2+1] = fy;
      if (withmask) outp[2*BN + row] = mf;
    }
    atomicAdd(&g_cnt[slotM*B_ + b], mm);
  }
  if (lane == 0 && mm) atomicOr(&g_bitsM[row >> 5], 1u << (row & 31));
  if (lane == 0 && !mm) atomicAnd(&g_bitsM[row >> 5], ~(1u << (row & 31)));
}

// ---------------- dedup (+finish on final round) ----------
__global__ void k_dedup(const float* __restrict__ xy1, const float* __restrict__ xy2,
                        int dofinish, int slotM){
  __shared__ int cnt[N_+1];
  int b = blockIdx.x, tid = threadIdx.x;
  for (int s = tid; s < N_+1; s += 1024) cnt[s] = 0;
  __syncthreads();
  int v0 = g_idx1[b*N_ + tid], v1 = g_idx1[b*N_ + tid + 1024];
  atomicAdd(&cnt[v0], 1); atomicAdd(&cnt[v1], 1);
  __syncthreads();
  if (cnt[v0] > 1){ v0 = 0; g_idx1[b*N_ + tid] = 0; }
  if (cnt[v1] > 1){ v1 = 0; g_idx1[b*N_ + tid + 1024] = 0; }
  if (!dofinish) return;
  int vv[2] = {v0, v1};
  #pragma unroll
  for (int rr=0; rr<2; rr++){
    int i = tid + rr*1024, row = b*N_ + i;
    int v = vv[rr];
    int mm = (v != 0);
    int j = (v - 1) * mm;
    float mf = (float)mm;
    float fx = __fmul_rn(__fsub_rn(xy2[(b*N_+j)*2],   xy1[row*2]),   mf);
    float fy = __fmul_rn(__fsub_rn(xy2[(b*N_+j)*2+1], xy1[row*2+1]), mf);
    g_flowF[row*2] = fx; g_flowF[row*2+1] = fy;
    g_mask[row] = mm;
    unsigned bal = __ballot_sync(0xffffffffu, mm);
    if ((threadIdx.x & 31) == 0){
      g_bitsM[row >> 5] = bal;
      atomicAdd(&g_cnt[slotM*B_ + b], __popc(bal));
    }
  }
}

// ---------------- masked top-4 via list filter (+fallback) + IDW + xy11 prep -------
__global__ void k_griddata(int slot){
  __shared__ unsigned long long sb[WPB*128];
  int w = threadIdx.x >> 5;
  int lane = threadIdx.x & 31;
  int row = blockIdx.x*WPB + w;
  if (row >= BN) return;
  int b = row >> 11;

  int ei = g_nn1i[row*32+lane];
  float ed = g_nn1d[row*32+lane];
  bool okm = (g_mask[b*N_+ei] != 0);
  unsigned bal = __ballot_sync(0xffffffffu, okm);
  int avail = __popc(bal);
  int total = g_cnt[slot*B_ + b];
  int needed = total < 4 ? total : 4;

  unsigned long long out[4];
  if (avail >= needed){
    unsigned rem = bal;
    #pragma unroll
    for (int s=0; s<4; s++){
      if (rem){
        int l = __ffs(rem) - 1; rem &= rem - 1;
        float dd = __shfl_sync(0xffffffffu, ed, l);
        int jj = __shfl_sync(0xffffffffu, ei, l);
        out[s] = ((unsigned long long)__float_as_uint(dd) << 32) | (unsigned)jj;
      } else out[s] = 0x7F800000FFFFFFFFull;
    }
  } else {
    warp_topk2<4,128,true,false,false>(g_xy1p, g_xy1p, g_bitsM, row, sb + w*128, out);
  }

  if (lane == 0){
    float ws = 0.f, sx = 0.f, sy = 0.f;
    #pragma unroll
    for (int s=0; s<4; s++){
      float d = __uint_as_float((unsigned)(out[s] >> 32));
      float vf = (d < 5e8f) ? 1.0f : 0.0f;
      int j = (d < 5e8f) ? (int)(out[s] & 0xFFFFFFFFu) : 0;
      float wt = __fdiv_rn(vf, __fadd_rn(d, 1e-6f));
      sx = __fmaf_rn(wt, g_flowF[(b*N_+j)*2],   sx);
      sy = __fmaf_rn(wt, g_flowF[(b*N_+j)*2+1], sy);
      ws = __fadd_rn(ws, wt);
    }
    float ix = __fdiv_rn(sx, __fadd_rn(ws, EPSF));
    float iy = __fdiv_rn(sy, __fadd_rn(ws, EPSF));
    int m = g_mask[row];
    float gx = m ? g_flowF[row*2]   : ix;
    float gy = m ? g_flowF[row*2+1] : iy;
    float4 p = g_xy1p[row];
    float nx = __fadd_rn(p.x, gx);
    float ny = __fadd_rn(p.y, gy);
    g_xy11p[row] = make_float4(nx, ny, __fmaf_rn(ny, ny, __fmul_rn(nx, nx)), 0.f);
  }
}

// ---------------- dual knn_match scans: row top-2 and col top-1 (D space) ----------
__global__ void k_knn21(){
  __shared__ unsigned long long sb[WPB*128];
  int w = threadIdx.x >> 5;
  int row2 = blockIdx.x*WPB + w;
  if (row2 >= 2*BN) return;
  bool first = row2 < BN;
  int row = first ? row2 : row2 - BN;
  const float4* Q = first ? g_xy11p : g_xy2p;
  const float4* R = first ? g_xy2p  : g_xy11p;
  unsigned long long out[2];
  warp_topk2<2,128,false,false,true>(Q, R, nullptr, row, sb + w*128, out);
  if ((threadIdx.x & 31) == 0){
    if (first){
      g_rowIdx[row*2]   = (int)(out[0] & 0xFFFFFFFFu);
      g_rowIdx[row*2+1] = (int)(out[1] & 0xFFFFFFFFu);
      g_rowD[row*2]   = __uint_as_float((unsigned)(out[0] >> 32));
      g_rowD[row*2+1] = __uint_as_float((unsigned)(out[1] >> 32));
    } else {
      g_colArg[row] = (int)(out[0] & 0xFFFFFFFFu);
    }
  }
}

// ---------------- host orchestration ----------------
extern "C" void kernel_launch(void* const* d_in, const int* in_sizes, int n_in,
                              void* d_out, int out_size){
  const float* xy1 = (const float*)d_in[0];
  const float* xy2 = (const float*)d_in[1];
  const float* f1  = (const float*)d_in[2];
  const float* f2  = (const float*)d_in[3];
  const float* gam = (const float*)d_in[4];
  const float* eps = (const float*)d_in[5];
  float* outp = (float*)d_out;
  int withmask = (out_size >= BN*3) ? 1 : 0;

  static bool attr_done = false;
  if (!attr_done){
    cudaFuncSetAttribute(k_sinkhorn_all, cudaFuncAttributeMaxDynamicSharedMemorySize, 81920);
    attr_done = true;
  }

  const int WB = WPB*32;            // 256 threads
  const int GW = BN/WPB;            // 512 blocks
  const int GW2 = 2*BN/WPB;         // 1024 blocks
  const int TBs = 64, GTs = BN/TBs; // simmerge spread: 64 blocks of 64 threads

  int slotA = 0;    // counts of maskA (outlier consumers)
  int slotM = 10;   // counts of mask (griddata consumers)

  k_init<<<(2*BN*32)/256, 256>>>(f1, f2, gam, eps, xy1, xy2);
  k_knnpre<<<GW2, WB>>>();

  // ---- two sinkhorn matching passes ----
  for (int pass = 0; pass < 2; pass++){
    k_knn4kc<<<GW, WB>>>(pass);
    k_sinkhorn_all<<<dim3(B_,4), 1024, 81920>>>();
    for (int r = 0; r < 4; r++){
      if (r == 0) k_simmerge<8,0><<<GTs, TBs>>>(xy1, xy2, r, slotA);
      else        k_simmerge<8,1><<<GTs, TBs>>>(xy1, xy2, r, slotA);
      k_outlier<<<GW, WB>>>(slotA);
      slotA++;
      if (r > 0) k_dedup<<<2, 1024>>>(xy1, xy2, r == 3, slotM);
    }
    k_griddata<<<GW, WB>>>(slotM);
    slotM++;
  }

  // ---- two KNN matching passes ----
  for (int pass = 0; pass < 2; pass++){
    int final = (pass == 1);
    k_knn21<<<GW2, WB>>>();
    k_simmerge<11,2><<<GTs, TBs>>>(xy1, xy2, 0, slotA);
    k_outlierF<<<GW, WB>>>(xy1, xy2, slotA, slotM,
                           final ? outp : nullptr, withmask);
    slotA++;
    if (!final){
      k_griddata<<<GW, WB>>>(slotM);
      slotM++;
    }
  }
}

// round 17
// speedup vs baseline: 1.0305x; 1.0103x over previous
#include <cuda_runtime.h>
#include <stdint.h>
#include <math.h>

#define N_   2048
#define B_   2
#define C_   512
#define BN   (B_*N_)
#define EPSF 1e-8f
#define BIGF 1e9f
#define WPB  8          // warps per scan block

// ---------------- device scratch ----------------
__device__ float  g_f1n[BN*C_], g_f2n[BN*C_];
__device__ float4 g_xy1p[BN], g_xy2p[BN], g_xy11p[BN];   // (x, y, rb, 0)
__device__ int    g_nbA[BN*12], g_nbB[BN*12];
__device__ unsigned long long g_nn1k[BN*32];   // packed (d2bits<<32)|j
__device__ int    g_cand[BN*4];
__device__ float  g_Kc[BN*4];
__device__ int    g_sord[BN];
__device__ int    g_idx0R[4*BN];
__device__ int    g_idxA[BN], g_maskA[BN], g_idx1[BN], g_mask[BN];
__device__ unsigned g_bitsA[B_*(N_/32)], g_bitsM[B_*(N_/32)];
__device__ int    g_cnt[64];
__device__ float  g_flow[BN*2];    // simmerge output (pre-outlier)
__device__ float  g_flowF[BN*2];   // finish output (post-dedup/keep)
__device__ float  g_rowD[BN*2];
__device__ int    g_rowIdx[BN*2];
__device__ int    g_colArg[BN];
__device__ float  g_par[2];   // [0]=eps, [1]=power

// ---------------- init: params + counters + point prep + feature normalize --------
__global__ void k_init(const float* __restrict__ f1, const float* __restrict__ f2,
                       const float* __restrict__ gam, const float* __restrict__ eps,
                       const float* __restrict__ xy1, const float* __restrict__ xy2){
  int gt = blockIdx.x*blockDim.x + threadIdx.x;
  int gw = gt >> 5;
  int lane = threadIdx.x & 31;
  if (gt < 64) g_cnt[gt] = 0;
  if (gt == 64){
    float e = __fadd_rn(expf(eps[0]), 0.03f);
    float g = expf(gam[0]);
    g_par[0] = e;
    g_par[1] = __fdiv_rn(g, __fadd_rn(g, e));
  }
  if (gt < 2*BN){
    bool is1 = gt < BN;
    int row = is1 ? gt : gt - BN;
    const float* xy = is1 ? xy1 : xy2;
    float x = xy[row*2], y = xy[row*2+1];
    float4 v = make_float4(x, y, __fmaf_rn(y, y, __fmul_rn(x, x)), 0.f);
    if (is1) g_xy1p[row] = v; else g_xy2p[row] = v;
  }
  if (gw >= 2*BN) return;
  bool is1 = gw < BN;
  int row = is1 ? gw : gw - BN;
  const float* f = (is1 ? f1 : f2) + (size_t)row*C_;
  float*       o = (is1 ? g_f1n : g_f2n) + (size_t)row*C_;
  float v[16];
  float s = 0.f;
  #pragma unroll
  for (int t=0; t<16; t++){ v[t] = f[lane + 32*t]; s = __fmaf_rn(v[t], v[t], s); }
  #pragma unroll
  for (int off=16; off; off>>=1) s = __fadd_rn(s, __shfl_xor_sync(0xffffffffu, s, off));
  float n = __fadd_rn(sqrtf(s), EPSF);
  #pragma unroll
  for (int t=0; t<16; t++) o[lane + 32*t] = __fdiv_rn(v[t], n);
}

// ---------------- fallback: insertion-sort warp top-K (rare; bit-identical) --------
template<int K, bool MASKC, bool EYE, bool SQRT>
__device__ __noinline__ void warp_topk_ins(
    const float4* __restrict__ Q, const float4* __restrict__ R,
    const unsigned* __restrict__ mbits, int row, unsigned long long (&out)[K])
{
  const unsigned FULL = 0xffffffffu;
  int lane = threadIdx.x & 31;
  int b = row >> 11, i = row & (N_-1);
  float4 q = __ldg(&Q[row]);
  const float4* Rb = R + (size_t)b*N_;
  unsigned w0 = FULL, w1 = FULL;
  if (MASKC){
    const unsigned* mb = mbits + b*(N_/32);
    w0 = __ldg(&mb[lane]); w1 = __ldg(&mb[32+lane]);
  }
  unsigned long long best[K];
  #pragma unroll
  for (int s=0; s<K; s++) best[s] = 0x7F800000FFFFFFFFull;
  float dlast = __uint_as_float(0x7F800000u);
  float U     = __uint_as_float(0x7FC00000u);

  for (int t=0; t<64; t++){
    int j = lane + 32*t;
    float4 r = __ldg(&Rb[j]);
    float dt = __fmaf_rn(q.y, r.y, __fmul_rn(q.x, r.x));
    float d  = fmaxf(__fsub_rn(__fadd_rn(q.z, r.z), __fmul_rn(2.0f, dt)), 0.0f);
    if (MASKC){
      unsigned wv = __shfl_sync(FULL, (t<32)?w0:w1, t&31);
      if (!((wv>>lane)&1u)) d = BIGF;
    }
    if (EYE){ if (j == i) d = __fadd_rn(d, BIGF); }
    bool try_ins;
    if (SQRT){
      float d2pe = __fadd_rn(d, EPSF);
      try_ins = !(d2pe > U);
      if (try_ins) d = sqrtf(d2pe);
    } else try_ins = (d <= dlast);
    if (try_ins){
      unsigned long long key = ((unsigned long long)__float_as_uint(d) << 32) | (unsigned)j;
      if (key < best[K-1]){
        best[K-1] = key;
        #pragma unroll
        for (int s=K-1; s>0; s--){
          if (best[s] < best[s-1]){
            unsigned long long tmp = best[s-1]; best[s-1] = best[s]; best[s] = tmp;
          } else break;
        }
        unsigned hb = (unsigned)(best[K-1] >> 32);
        if (SQRT){
          float up = __uint_as_float(hb + 1);
          U = __fmul_ru(up, up);
        } else dlast = __uint_as_float(hb);
      }
    }
  }
  #pragma unroll
  for (int s=0; s<K; s++){
    unsigned long long c = best[0];
    unsigned long long m = c;
    #pragma unroll
    for (int off=16; off; off>>=1){
      unsigned long long o = __shfl_xor_sync(FULL, m, off);
      m = (o < m) ? o : m;
    }
    if (c == m){
      #pragma unroll
      for (int u=0; u<K-1; u++) best[u] = best[u+1];
      best[K-1] = 0x7F800000FFFFFFFFull;
    }
    out[s] = m;
  }
}

// ---------------- two-phase divergence-free exact warp top-K ----------------
template<int K, int CAP, bool MASKC, bool EYE, bool SQRT>
__device__ __forceinline__ void warp_topk2(
    const float4* __restrict__ Q, const float4* __restrict__ R,
    const unsigned* __restrict__ mbits, int row,
    unsigned long long* __restrict__ sbuf, unsigned long long (&out)[K])
{
  const unsigned FULL = 0xffffffffu;
  const unsigned long long INFK = 0x7F800000FFFFFFFFull;
  int lane = threadIdx.x & 31;
  int b = row >> 11, i = row & (N_-1);
  float4 q = __ldg(&Q[row]);
  const float4* Rb = R + (size_t)b*N_;
  unsigned w0 = FULL, w1 = FULL;
  if (MASKC){
    const unsigned* mb = mbits + b*(N_/32);
    w0 = __ldg(&mb[lane]); w1 = __ldg(&mb[32+lane]);
  }

  float mn = __uint_as_float(0x7F800000u);
  #pragma unroll 4
  for (int t=0; t<64; t++){
    int j = lane + 32*t;
    float4 r = __ldg(&Rb[j]);
    float dt = __fmaf_rn(q.y, r.y, __fmul_rn(q.x, r.x));
    float d  = fmaxf(__fsub_rn(__fadd_rn(q.z, r.z), __fmul_rn(2.0f, dt)), 0.0f);
    if (MASKC){
      unsigned wv = __shfl_sync(FULL, (t<32)?w0:w1, t&31);
      if (!((wv>>lane)&1u)) d = BIGF;
    }
    if (EYE){ if (j == i) d = __fadd_rn(d, BIGF); }
    mn = fminf(mn, d);
  }
  float v = mn, tau = 0.f;
  #pragma unroll
  for (int s=0; s<K; s++){
    float g = v;
    #pragma unroll
    for (int off=16; off; off>>=1) g = fminf(g, __shfl_xor_sync(FULL, g, off));
    tau = g;
    unsigned hit = __ballot_sync(FULL, v == g);
    if (lane == (__ffs(hit)-1)) v = __uint_as_float(0x7F800000u);
  }
  float ub = 0.f;
  if (SQRT){
    float S  = sqrtf(__fadd_rn(tau, EPSF));
    float su = __uint_as_float(__float_as_uint(S) + 1);
    ub = __fmul_ru(su, su);
  }

  int cnt = 0;
  #pragma unroll 4
  for (int t=0; t<64; t++){
    int j = lane + 32*t;
    float4 r = __ldg(&Rb[j]);
    float dt = __fmaf_rn(q.y, r.y, __fmul_rn(q.x, r.x));
    float d  = fmaxf(__fsub_rn(__fadd_rn(q.z, r.z), __fmul_rn(2.0f, dt)), 0.0f);
    if (MASKC){
      unsigned wv = __shfl_sync(FULL, (t<32)?w0:w1, t&31);
      if (!((wv>>lane)&1u)) d = BIGF;
    }
    if (EYE){ if (j == i) d = __fadd_rn(d, BIGF); }
    bool acc;
    if (SQRT) acc = (__fadd_rn(d, EPSF) < ub);
    else      acc = (d <= tau);
    unsigned bal = __ballot_sync(FULL, acc);
    if (acc){
      int pos = cnt + __popc(bal & ((1u<<lane)-1u));
      if (pos < CAP){
        float kd = SQRT ? sqrtf(__fadd_rn(d, EPSF)) : d;
        sbuf[pos] = ((unsigned long long)__float_as_uint(kd) << 32) | (unsigned)j;
      }
    }
    cnt += __popc(bal);
  }
  if (cnt > CAP){
    warp_topk_ins<K,MASKC,EYE,SQRT>(Q, R, mbits, row, out);
    return;
  }
  __syncwarp();
  unsigned long long mk[CAP/32];
  #pragma unroll
  for (int u=0; u<CAP/32; u++){
    int idx = lane + 32*u;
    mk[u] = (idx < cnt) ? sbuf[idx] : INFK;
  }
  #pragma unroll
  for (int s=0; s<K; s++){
    unsigned long long lm = mk[0]; int slot = 0;
    #pragma unroll
    for (int u=1; u<CAP/32; u++) if (mk[u] < lm){ lm = mk[u]; slot = u; }
    unsigned long long g = lm;
    #pragma unroll
    for (int off=16; off; off>>=1){
      unsigned long long o = __shfl_xor_sync(FULL, g, off);
      g = (o < g) ? o : g;
    }
    out[s] = g;
    if (lm == g){
      #pragma unroll
      for (int u=0; u<CAP/32; u++) if (u == slot) mk[u] = INFK;
    }
  }
}

// ---------------- precompute: top-32 self list on xy1 (+nbA), top-12 on xy2 --------
__global__ void k_knnpre(){
  __shared__ unsigned long long sb[WPB*256];
  int w = threadIdx.x >> 5;
  int row2 = blockIdx.x*WPB + w;
  if (row2 >= 2*BN) return;
  if (row2 < BN){
    int row = row2;
    unsigned long long out[32];
    warp_topk2<32,256,false,false,false>(g_xy1p, g_xy1p, nullptr, row, sb + w*256, out);
    if ((threadIdx.x & 31) == 0){
      #pragma unroll
      for (int s=0; s<32; s++){
        g_nn1k[row*32+s] = out[s];
        if (s < 12) g_nbA[row*12+s] = (int)(out[s] & 0xFFFFFFFFu);
      }
    }
  } else {
    int row = row2 - BN;
    unsigned long long out[12];
    warp_topk2<12,128,false,false,false>(g_xy2p, g_xy2p, nullptr, row, sb + w*256, out);
    if ((threadIdx.x & 31) == 0){
      #pragma unroll
      for (int s=0; s<12; s++) g_nbB[row*12+s] = (int)(out[s] & 0xFFFFFFFFu);
    }
  }
}

// ---------------- knn4 candidates + feature K entries + slot order (fused) --------
__global__ void k_knn4kc(int useflow){
  __shared__ unsigned long long sb[WPB*128];
  int w = threadIdx.x >> 5;
  int lane = threadIdx.x & 31;
  int row = blockIdx.x*WPB + w;
  if (row >= BN) return;
  int b = row >> 11;
  const float4* Q = useflow ? g_xy11p : g_xy1p;
  unsigned long long out[4];
  warp_topk2<4,128,false,false,false>(Q, g_xy2p, nullptr, row, sb + w*128, out);

  const float* f1 = g_f1n + (size_t)row*C_;
  float a[16];
  #pragma unroll
  for (int t=0; t<16; t++) a[t] = f1[lane + 32*t];
  float eps = g_par[0];
  #pragma unroll
  for (int c=0; c<4; c++){
    int j = (int)(out[c] & 0xFFFFFFFFu);
    const float* f2 = g_f2n + ((size_t)(b*N_ + j))*C_;
    float s = 0.f;
    #pragma unroll
    for (int t=0; t<16; t++) s = __fadd_rn(s, __fmul_rn(a[t], __ldg(&f2[lane + 32*t])));
    #pragma unroll
    for (int off=16; off; off>>=1) s = __fadd_rn(s, __shfl_xor_sync(0xffffffffu, s, off));
    if (lane == 0){
      g_cand[row*4+c] = j;
      g_Kc[row*4+c] = expf(__fdiv_rn(-(__fsub_rn(1.0f, s)), eps));
    }
  }
  if (lane == 0){
    int k0 = ((int)(out[0]&0xFFFFFFFFu)<<2)|0, k1 = ((int)(out[1]&0xFFFFFFFFu)<<2)|1;
    int k2 = ((int)(out[2]&0xFFFFFFFFu)<<2)|2, k3 = ((int)(out[3]&0xFFFFFFFFu)<<2)|3;
    int t;
    if (k0>k1){t=k0;k0=k1;k1=t;} if (k2>k3){t=k2;k2=k3;k3=t;}
    if (k0>k2){t=k0;k0=k2;k2=t;} if (k1>k3){t=k1;k1=k3;k3=t;}
    if (k1>k2){t=k1;k1=k2;k2=t;}
    g_sord[row] = (k0&3) | ((k1&3)<<2) | ((k2&3)<<4) | ((k3&3)<<6);
  }
}

// ---------------- all 4 sinkhorn rounds in one launch ----------
__global__ void k_sinkhorn_all(){
  extern __shared__ char sm[];
  unsigned long long* ck = (unsigned long long*)sm;
  float* su  = (float*)(sm + 16384);
  float* sv  = (float*)(sm + 24576);
  int*   tl  = (int*)(sm + 32768);
  int*   coff= (int*)(sm + 65536);
  int*   ccnt= (int*)(sm + 73728);
  int*   scnt= (int*)ck;
  int*   scur= scnt + N_;

  int b = blockIdx.x, r = blockIdx.y, dr0 = r + 1, tid = threadIdx.x;
  const int* cb = g_cand + b*N_*4;
  const float* Kb = g_Kc + b*N_*4;
  const int* sob = g_sord + b*N_;
  const float P = 1.0f/2048.0f;
  float pw = g_par[1];

  scnt[tid] = 0; scnt[tid+1024] = 0;
  __syncthreads();
  #pragma unroll
  for (int rr=0; rr<2; rr++){
    int i = tid + rr*1024;
    #pragma unroll
    for (int c=0; c<4; c++) atomicAdd(&scnt[cb[i*4+c]], 1);
  }
  __syncthreads();
  if (tid < 32){
    int lo = tid*64, tot = 0;
    for (int t=0; t<64; t++) tot += scnt[lo+t];
    int inc = tot;
    #pragma unroll
    for (int off=1; off<32; off<<=1){
      int v = __shfl_up_sync(0xffffffffu, inc, off);
      if (tid >= off) inc += v;
    }
    int run = inc - tot;
    for (int t=0; t<64; t++){
      coff[lo+t] = run;
      ccnt[lo+t] = scnt[lo+t];
      run += scnt[lo+t];
    }
  }
  __syncthreads();
  scur[tid] = coff[tid]; scur[tid+1024] = coff[tid+1024];
  __syncthreads();
  #pragma unroll
  for (int rr=0; rr<2; rr++){
    int i = tid + rr*1024;
    #pragma unroll
    for (int c=0; c<4; c++){
      int j = cb[i*4+c];
      int pos = atomicAdd(&scur[j], 1);
      tl[pos] = (i<<2) | c;
    }
  }
  __syncthreads();
  #pragma unroll
  for (int rr=0; rr<2; rr++){
    int col = tid + rr*1024;
    int off = coff[col], cnt = ccnt[col];
    int* L = tl + off;
    for (int a2=1; a2<cnt; a2++){
      int v = L[a2]; int p = a2-1;
      while (p >= 0 && L[p] > v){ L[p+1] = L[p]; p--; }
      L[p+1] = v;
    }
  }
  __syncthreads();

  sv[tid] = 1.f; sv[tid+1024] = 1.f;
  __syncthreads();
  for (int t=0; t<5; t++){
    #pragma unroll
    for (int rr=0; rr<2; rr++){
      int i = tid + rr*1024;
      int o = sob[i];
      float s = 0.f;
      #pragma unroll
      for (int p=0; p<4; p++){
        int sl = (o >> (2*p)) & 3;
        if (sl < dr0)
          s = __fmaf_rn(Kb[i*4+sl], sv[cb[i*4+sl]], s);
      }
      su[i] = powf(__fdiv_rn(P, __fadd_rn(s, EPSF)), pw);
    }
    __syncthreads();
    #pragma unroll
    for (int rr=0; rr<2; rr++){
      int j = tid + rr*1024;
      int off = coff[j], cnt = ccnt[j];
      float s = 0.f;
      for (int p=0; p<cnt; p++){
        int e = tl[off+p];
        int c = e & 3;
        if (c < dr0){
          int i = e >> 2;
          s = __fmaf_rn(Kb[i*4+c], su[i], s);
        }
      }
      sv[j] = powf(__fdiv_rn(P, __fadd_rn(s, EPSF)), pw);
    }
    __syncthreads();
  }

  ck[tid] = 0xFFFFFFFFull; ck[tid+1024] = 0xFFFFFFFFull;
  __syncthreads();
  #pragma unroll
  for (int rr=0; rr<2; rr++){
    int i = tid + rr*1024;
    float ui = su[i];
    for (int c=0; c<dr0; c++){
      int j = cb[i*4+c];
      float tv = __fmul_rn(__fmul_rn(ui, Kb[i*4+c]), sv[j]);
      unsigned long long key = ((unsigned long long)__float_as_uint(tv) << 32)
                             | (unsigned)(~(unsigned)i);
      atomicMax(&ck[j], key);
    }
  }
  __syncthreads();
  #pragma unroll
  for (int rr=0; rr<2; rr++){
    int i = tid + rr*1024;
    float ui = su[i];
    unsigned long long k0 = 0ull, k1 = 0ull;
    for (int c=0; c<dr0; c++){
      int j = cb[i*4+c];
      float tv = __fmul_rn(__fmul_rn(ui, Kb[i*4+c]), sv[j]);
      unsigned long long key = ((unsigned long long)__float_as_uint(tv) << 32)
                             | (unsigned)(~(unsigned)j);
      if (key > k0){ k1 = k0; k0 = key; }
      else if (key > k1){ k1 = key; }
    }
    float rv0 = __uint_as_float((unsigned)(k0 >> 32));
    float rv1 = __uint_as_float((unsigned)(k1 >> 32));
    int bj = (int)(~(unsigned)k0);
    int bi = (int)(~(unsigned)ck[bj]);
    bool ok = rv0 > __fmul_rn(1.2f, rv1);
    g_idx0R[r*BN + b*N_ + i] = (bi == i && ok) ? bj : -1;
  }
}

// ---------------- merge (+optional knn recon) + similarity verify + bitpack+count ---
template<int SIMK, int MODE>
__global__ void k_simmerge(const float* __restrict__ xy1, const float* __restrict__ xy2,
                           int r, int slot){
  int row = blockIdx.x*blockDim.x + threadIdx.x;
  int b = row / N_, i = row - b*N_;
  int m;
  if (MODE == 0) m = g_idx0R[r*BN + row];
  else if (MODE == 1){ int p = g_idx1[row]; m = (p == 0) ? g_idx0R[r*BN + row] : (p - 1); }
  else {
    float d0 = g_rowD[row*2], d1 = g_rowD[row*2+1];
    int bj = g_rowIdx[row*2];
    bool ok = __fmul_rn(d0, 1.2f) < d1;
    bool mut = (g_colArg[b*N_ + bj] == i);
    m = (ok && mut) ? bj : -1;
  }

  int outv = -1;
  if (m >= 0){
    const float* X1 = xy1 + (size_t)b*N_*2;
    const float* X2 = xy2 + (size_t)b*N_*2;
    float pix = X1[i*2], piy = X1[i*2+1];
    float pjx = X2[m*2], pjy = X2[m*2+1];
    float o1x[SIMK], o1y[SIMK], o2x[SIMK], o2y[SIMK];
    #pragma unroll
    for (int k=0; k<SIMK; k++){
      int a = g_nbA[row*12 + 1 + k];
      o1x[k] = __fsub_rn(X1[a*2],   pix);
      o1y[k] = __fsub_rn(X1[a*2+1], piy);
      int c = g_nbB[(b*N_+m)*12 + 1 + k];
      o2x[k] = __fsub_rn(X2[c*2],   pjx);
      o2y[k] = __fsub_rn(X2[c*2+1], pjy);
    }
    float colmin[SIMK];
    #pragma unroll
    for (int l=0; l<SIMK; l++) colmin[l] = 3.4e38f;
    float sum1 = 0.f;
    #pragma unroll
    for (int k=0; k<SIMK; k++){
      float rmn = 3.4e38f;
      #pragma unroll
      for (int l=0; l<SIMK; l++){
        float dx = __fsub_rn(o1x[k], o2x[l]);
        float dy = __fsub_rn(o1y[k], o2y[l]);
        float d = sqrtf(__fadd_rn(__fmaf_rn(dy, dy, __fmul_rn(dx, dx)), EPSF));
        rmn = fminf(rmn, d);
        colmin[l] = fminf(colmin[l], d);
      }
      sum1 = __fadd_rn(sum1, rmn);
    }
    float sum2 = 0.f;
    #pragma unroll
    for (int l=0; l<SIMK; l++) sum2 = __fadd_rn(sum2, colmin[l]);
    float Kf = (float)SIMK;
    float cham = __fmul_rn(0.5f, __fadd_rn(__fdiv_rn(sum1, Kf), __fdiv_rn(sum2, Kf)));
    if (cham <= 2.0f) outv = m;
  }
  g_idxA[row] = outv;
  int mm = (outv >= 0);
  g_maskA[row] = mm;
  int j = (outv >= 0) ? outv : 0;
  float mf = (float)mm;
  g_flow[row*2]   = __fmul_rn(__fsub_rn(xy2[(b*N_+j)*2],   xy1[row*2]),   mf);
  g_flow[row*2+1] = __fmul_rn(__fsub_rn(xy2[(b*N_+j)*2+1], xy1[row*2+1]), mf);
  unsigned bal = __ballot_sync(0xffffffffu, mm);
  if ((threadIdx.x & 31) == 0){
    g_bitsA[row >> 5] = bal;
    atomicAdd(&g_cnt[slot*B_ + b], __popc(bal));
  }
}

// ---------------- shared outlier core: masked top-8+eye filter + keep decision -----
__device__ __forceinline__ int outlier_keep(int row, int b, int i, int mi, int slot,
                                            unsigned long long* sbw){
  int lane = threadIdx.x & 31;
  unsigned long long kk = g_nn1k[row*32+lane];
  int ei = (int)(kk & 0xFFFFFFFFu);
  bool okm = (ei != i) && (g_maskA[b*N_+ei] != 0);
  unsigned bal = __ballot_sync(0xffffffffu, okm);
  int avail = __popc(bal);
  int total = g_cnt[slot*B_ + b] - mi;
  int needed = total < 8 ? total : 8;

  unsigned long long out[8];
  if (avail >= needed){
    unsigned rem = bal;
    #pragma unroll
    for (int s=0; s<8; s++){
      if (rem){
        int l = __ffs(rem) - 1; rem &= rem - 1;
        out[s] = __shfl_sync(0xffffffffu, kk, l);
      } else out[s] = 0x7F800000FFFFFFFFull;
    }
  } else {
    warp_topk2<8,128,true,true,false>(g_xy1p, g_xy1p, g_bitsA, row, sbw, out);
  }

  if (lane != 0) return 0;
  float fx = g_flow[row*2], fy = g_flow[row*2+1];
  float sx = 0.f, sy = 0.f, cnt = 0.f;
  #pragma unroll
  for (int s=0; s<8; s++){
    float d = __uint_as_float((unsigned)(out[s] >> 32));
    float vf = (d < 5e8f) ? 1.0f : 0.0f;
    int j = (d < 5e8f) ? (int)(out[s] & 0xFFFFFFFFu) : 0;
    sx = __fmaf_rn(g_flow[(b*N_+j)*2],   vf, sx);
    sy = __fmaf_rn(g_flow[(b*N_+j)*2+1], vf, sy);
    cnt = __fadd_rn(cnt, vf);
  }
  float dv = fmaxf(cnt, 1.0f);
  float mx = __fdiv_rn(sx, dv), my = __fdiv_rn(sy, dv);
  float ddx = __fsub_rn(fx, mx), ddy = __fsub_rn(fy, my);
  float dev = sqrtf(__fadd_rn(__fmaf_rn(ddy, ddy, __fmul_rn(ddx, ddx)), EPSF));
  bool keep = mi && ((cnt > 0.0f) ? (dev <= 2.0f) : true);
  return keep ? (g_idxA[row] + 1) : 0;
}

// ---------------- outlier only (sink-pass rounds) ----------
__global__ void k_outlier(int slot){
  __shared__ unsigned long long sb[WPB*128];
  int w = threadIdx.x >> 5;
  int row = blockIdx.x*WPB + w;
  if (row >= BN) return;
  int b = row >> 11, i = row & (N_-1);
  int mi = g_maskA[row];
  int v = outlier_keep(row, b, i, mi, slot, sb + w*128);
  if ((threadIdx.x & 31) == 0) g_idx1[row] = v;
}

// ---------------- outlier + finish fused (knn passes; idx1 local to row) ----------
__global__ void k_outlierF(const float* __restrict__ xy1, const float* __restrict__ xy2,
                           int slot, int slotM, float* __restrict__ outp, int withmask){
  __shared__ unsigned long long sb[WPB*128];
  int w = threadIdx.x >> 5;
  int row = blockIdx.x*WPB + w;
  if (row >= BN) return;
  int b = row >> 11, i = row & (N_-1);
  int mi = g_maskA[row];
  int v = outlier_keep(row, b, i, mi, slot, sb + w*128);
  int lane = threadIdx.x & 31;
  int mm = 0;
  if (lane == 0){
    g_idx1[row] = v;
    mm = (v != 0);
    int j = (v - 1) * mm;
    float mf = (float)mm;
    float fx = __fmul_rn(__fsub_rn(xy2[(b*N_+j)*2],   xy1[row*2]),   mf);
    float fy = __fmul_rn(__fsub_rn(xy2[(b*N_+j)*2+1], xy1[row*2+1]), mf);
    g_flowF[row*2] = fx; g_flowF[row*2+1] = fy;
    g_mask[row] = mm;
    if (outp){
      outp[row*2] = fx; outp[row*2+1] = fy;
      if (withmask) outp[2*BN + row] = mf;
    }
    atomicAdd(&g_cnt[slotM*B_ + b], mm);
  }
  if (lane == 0 && mm) atomicOr(&g_bitsM[row >> 5], 1u << (row & 31));
  if (lane == 0 && !mm) atomicAnd(&g_bitsM[row >> 5], ~(1u << (row & 31)));
}

// ---------------- dedup (+finish on final round) ----------
__global__ void k_dedup(const float* __restrict__ xy1, const float* __restrict__ xy2,
                        int dofinish, int slotM){
  __shared__ int cnt[N_+1];
  int b = blockIdx.x, tid = threadIdx.x;
  for (int s = tid; s < N_+1; s += 1024) cnt[s] = 0;
  __syncthreads();
  int v0 = g_idx1[b*N_ + tid], v1 = g_idx1[b*N_ + tid + 1024];
  atomicAdd(&cnt[v0], 1); atomicAdd(&cnt[v1], 1);
  __syncthreads();
  if (cnt[v0] > 1){ v0 = 0; g_idx1[b*N_ + tid] = 0; }
  if (cnt[v1] > 1){ v1 = 0; g_idx1[b*N_ + tid + 1024] = 0; }
  if (!dofinish) return;
  int vv[2] = {v0, v1};
  #pragma unroll
  for (int rr=0; rr<2; rr++){
    int i = tid + rr*1024, row = b*N_ + i;
    int v = vv[rr];
    int mm = (v != 0);
    int j = (v - 1) * mm;
    float mf = (float)mm;
    float fx = __fmul_rn(__fsub_rn(xy2[(b*N_+j)*2],   xy1[row*2]),   mf);
    float fy = __fmul_rn(__fsub_rn(xy2[(b*N_+j)*2+1], xy1[row*2+1]), mf);
    g_flowF[row*2] = fx; g_flowF[row*2+1] = fy;
    g_mask[row] = mm;
    unsigned bal = __ballot_sync(0xffffffffu, mm);
    if ((threadIdx.x & 31) == 0){
      g_bitsM[row >> 5] = bal;
      atomicAdd(&g_cnt[slotM*B_ + b], __popc(bal));
    }
  }
}

// ---------------- masked top-4 via list filter (+fallback) + IDW + xy11 prep -------
__global__ void k_griddata(int slot){
  __shared__ unsigned long long sb[WPB*128];
  int w = threadIdx.x >> 5;
  int lane = threadIdx.x & 31;
  int row = blockIdx.x*WPB + w;
  if (row >= BN) return;
  int b = row >> 11;

  unsigned long long kk = g_nn1k[row*32+lane];
  int ei = (int)(kk & 0xFFFFFFFFu);
  bool okm = (g_mask[b*N_+ei] != 0);
  unsigned bal = __ballot_sync(0xffffffffu, okm);
  int avail = __popc(bal);
  int total = g_cnt[slot*B_ + b];
  int needed = total < 4 ? total : 4;

  unsigned long long out[4];
  if (avail >= needed){
    unsigned rem = bal;
    #pragma unroll
    for (int s=0; s<4; s++){
      if (rem){
        int l = __ffs(rem) - 1; rem &= rem - 1;
        out[s] = __shfl_sync(0xffffffffu, kk, l);
      } else out[s] = 0x7F800000FFFFFFFFull;
    }
  } else {
    warp_topk2<4,128,true,false,false>(g_xy1p, g_xy1p, g_bitsM, row, sb + w*128, out);
  }

  if (lane == 0){
    float ws = 0.f, sx = 0.f, sy = 0.f;
    #pragma unroll
    for (int s=0; s<4; s++){
      float d = __uint_as_float((unsigned)(out[s] >> 32));
      float vf = (d < 5e8f) ? 1.0f : 0.0f;
      int j = (d < 5e8f) ? (int)(out[s] & 0xFFFFFFFFu) : 0;
      float wt = __fdiv_rn(vf, __fadd_rn(d, 1e-6f));
      sx = __fmaf_rn(wt, g_flowF[(b*N_+j)*2],   sx);
      sy = __fmaf_rn(wt, g_flowF[(b*N_+j)*2+1], sy);
      ws = __fadd_rn(ws, wt);
    }
    float ix = __fdiv_rn(sx, __fadd_rn(ws, EPSF));
    float iy = __fdiv_rn(sy, __fadd_rn(ws, EPSF));
    int m = g_mask[row];
    float gx = m ? g_flowF[row*2]   : ix;
    float gy = m ? g_flowF[row*2+1] : iy;
    float4 p = g_xy1p[row];
    float nx = __fadd_rn(p.x, gx);
    float ny = __fadd_rn(p.y, gy);
    g_xy11p[row] = make_float4(nx, ny, __fmaf_rn(ny, ny, __fmul_rn(nx, nx)), 0.f);
  }
}

// ---------------- dual knn_match scans: row top-2 and col top-1 (D space) ----------
__global__ void k_knn21(){
  __shared__ unsigned long long sb[WPB*128];
  int w = threadIdx.x >> 5;
  int row2 = blockIdx.x*WPB + w;
  if (row2 >= 2*BN) return;
  bool first = row2 < BN;
  int row = first ? row2 : row2 - BN;
  const float4* Q = first ? g_xy11p : g_xy2p;
  const float4* R = first ? g_xy2p  : g_xy11p;
  unsigned long long out[2];
  warp_topk2<2,128,false,false,true>(Q, R, nullptr, row, sb + w*128, out);
  if ((threadIdx.x & 31) == 0){
    if (first){
      g_rowIdx[row*2]   = (int)(out[0] & 0xFFFFFFFFu);
      g_rowIdx[row*2+1] = (int)(out[1] & 0xFFFFFFFFu);
      g_rowD[row*2]   = __uint_as_float((unsigned)(out[0] >> 32));
      g_rowD[row*2+1] = __uint_as_float((unsigned)(out[1] >> 32));
    } else {
      g_colArg[row] = (int)(out[0] & 0xFFFFFFFFu);
    }
  }
}

// ---------------- host orchestration ----------------
extern "C" void kernel_launch(void* const* d_in, const int* in_sizes, int n_in,
                              void* d_out, int out_size){
  const float* xy1 = (const float*)d_in[0];
  const float* xy2 = (const float*)d_in[1];
  const float* f1  = (const float*)d_in[2];
  const float* f2  = (const float*)d_in[3];
  const float* gam = (const float*)d_in[4];
  const float* eps = (const float*)d_in[5];
  float* outp = (float*)d_out;
  int withmask = (out_size >= BN*3) ? 1 : 0;

  static bool attr_done = false;
  if (!attr_done){
    cudaFuncSetAttribute(k_sinkhorn_all, cudaFuncAttributeMaxDynamicSharedMemorySize, 81920);
    attr_done = true;
  }

  const int WB = WPB*32;            // 256 threads
  const int GW = BN/WPB;            // 512 blocks
  const int GW2 = 2*BN/WPB;         // 1024 blocks
  const int TBs = 64, GTs = BN/TBs; // simmerge: 64 blocks of 64 threads

  int slotA = 0;    // counts of maskA (outlier consumers)
  int slotM = 10;   // counts of mask (griddata consumers)

  k_init<<<(2*BN*32)/256, 256>>>(f1, f2, gam, eps, xy1, xy2);
  k_knnpre<<<GW2, WB>>>();

  // ---- two sinkhorn matching passes ----
  for (int pass = 0; pass < 2; pass++){
    k_knn4kc<<<GW, WB>>>(pass);
    k_sinkhorn_all<<<dim3(B_,4), 1024, 81920>>>();
    for (int r = 0; r < 4; r++){
      if (r == 0) k_simmerge<8,0><<<GTs, TBs>>>(xy1, xy2, r, slotA);
      else        k_simmerge<8,1><<<GTs, TBs>>>(xy1, xy2, r, slotA);
      k_outlier<<<GW, WB>>>(slotA);
      slotA++;
      if (r > 0) k_dedup<<<2, 1024>>>(xy1, xy2, r == 3, slotM);
    }
    k_griddata<<<GW, WB>>>(slotM);
    slotM++;
  }

  // ---- two KNN matching passes ----
  for (int pass = 0; pass < 2; pass++){
    int final = (pass == 1);
    k_knn21<<<GW2, WB>>>();
    k_simmerge<11,2><<<GTs, TBs>>>(xy1, xy2, 0, slotA);
    k_outlierF<<<GW, WB>>>(xy1, xy2, slotA, slotM,
                           final ? outp : nullptr, withmask);
    slotA++;
    if (!final){
      k_griddata<<<GW, WB>>>(slotM);
      slotM++;
    }
  }
}